// round 4
// baseline (speedup 1.0000x reference)
#include <cuda_runtime.h>
#include <math_constants.h>

// Problem constants
#define BB 2
#define SQ 2048
#define EE 1024
#define HH 16
#define DD 64
#define MM (BB*SQ)   // 4096 rows

// Scratch (device globals: allocation-free rule)
__device__ float g_qh[BB*HH*SQ*DD];   // [B,H,S,D]
__device__ float g_kh[BB*HH*SQ*DD];
__device__ float g_vh[BB*HH*SQ*DD];
__device__ float g_att[BB*SQ*EE];     // attention context in [B,S,E]

// ---------------------------------------------------------------------------
// GEMM: C = A(MxK) @ W(NxK)^T (+bias). headmode=1 scatters to [B,H,S,D].
// 128x128 tile, BK=8, 256 threads, 8x8 register tile, 2-stage smem pipeline.
// ---------------------------------------------------------------------------
__global__ __launch_bounds__(256) void gemm_nt(
    const float* __restrict__ A, const float* __restrict__ W,
    const float* __restrict__ bias, float* __restrict__ C,
    int M, int N, int K, int headmode)
{
    __shared__ float As[2][8][128];
    __shared__ float Bs[2][8][128];
    const int m0 = blockIdx.y * 128;
    const int n0 = blockIdx.x * 128;
    const int tid = threadIdx.x;
    const int tr = tid >> 4;         // 0..15
    const int tc = tid & 15;         // 0..15
    const int lrow = tid >> 1;       // 0..127
    const int lseg = tid & 1;        // 0..1

    const float* Aptr = A + (size_t)(m0 + lrow) * K + lseg * 4;
    const float* Wptr = W + (size_t)(n0 + lrow) * K + lseg * 4;

    float acc[8][8];
    #pragma unroll
    for (int i = 0; i < 8; i++)
        #pragma unroll
        for (int j = 0; j < 8; j++) acc[i][j] = 0.f;

    // prologue: stage 0
    {
        float4 av = *(const float4*)(Aptr);
        float4 wv = *(const float4*)(Wptr);
        As[0][lseg*4+0][lrow] = av.x; As[0][lseg*4+1][lrow] = av.y;
        As[0][lseg*4+2][lrow] = av.z; As[0][lseg*4+3][lrow] = av.w;
        Bs[0][lseg*4+0][lrow] = wv.x; Bs[0][lseg*4+1][lrow] = wv.y;
        Bs[0][lseg*4+2][lrow] = wv.z; Bs[0][lseg*4+3][lrow] = wv.w;
    }
    __syncthreads();

    int cur = 0;
    for (int k0 = 0; k0 < K; k0 += 8) {
        const bool more = (k0 + 8) < K;
        float4 av2, wv2;
        if (more) {                       // prefetch next K-slab (LDG early)
            av2 = *(const float4*)(Aptr + k0 + 8);
            wv2 = *(const float4*)(Wptr + k0 + 8);
        }
        #pragma unroll
        for (int kk = 0; kk < 8; kk++) {
            float a[8], b[8];
            *(float4*)(a)   = *(float4*)&As[cur][kk][tr*8];
            *(float4*)(a+4) = *(float4*)&As[cur][kk][tr*8+4];
            *(float4*)(b)   = *(float4*)&Bs[cur][kk][tc*8];
            *(float4*)(b+4) = *(float4*)&Bs[cur][kk][tc*8+4];
            #pragma unroll
            for (int i = 0; i < 8; i++)
                #pragma unroll
                for (int j = 0; j < 8; j++)
                    acc[i][j] += a[i]*b[j];
        }
        if (more) {
            const int nxt = cur ^ 1;
            As[nxt][lseg*4+0][lrow] = av2.x; As[nxt][lseg*4+1][lrow] = av2.y;
            As[nxt][lseg*4+2][lrow] = av2.z; As[nxt][lseg*4+3][lrow] = av2.w;
            Bs[nxt][lseg*4+0][lrow] = wv2.x; Bs[nxt][lseg*4+1][lrow] = wv2.y;
            Bs[nxt][lseg*4+2][lrow] = wv2.z; Bs[nxt][lseg*4+3][lrow] = wv2.w;
        }
        __syncthreads();
        cur ^= 1;
    }

    #pragma unroll
    for (int i = 0; i < 8; i++) {
        const int m = m0 + tr*8 + i;
        #pragma unroll
        for (int j = 0; j < 8; j++) {
            const int n = n0 + tc*8 + j;
            float v = acc[i][j];
            if (bias) v += bias[n];
            if (headmode) {
                const int b = m >> 11, s = m & 2047;
                const int h = n >> 6,  d = n & 63;
                C[((size_t)(b*HH + h)*SQ + s)*DD + d] = v;
            } else {
                C[(size_t)m*N + n] = v;
            }
        }
    }
}

// ---------------------------------------------------------------------------
// Flash attention (causal + ALiBi), fp32. One CTA = (64 q-rows, one b,h).
// 64 threads as 8x8 grid, 8x8 micro-tiles (1.0 B LDS / FMA).
// Static smem 48KB; K-transposed and P-transposed alias one buffer.
// ---------------------------------------------------------------------------
__global__ __launch_bounds__(64, 4) void flash_kernel(
    const float* __restrict__ qh, const float* __restrict__ kh,
    const float* __restrict__ vh, float* __restrict__ att)
{
    __shared__ float Qt[64*64];    // [d][q]
    __shared__ float KPt[64*64];   // [d][c] for K, then [j][r] for P
    __shared__ float Vs[64*64];    // [j][c]

    const int qt = (SQ/64 - 1) - blockIdx.x;   // biggest tiles first
    const int h  = blockIdx.y;
    const int b  = blockIdx.z;
    const int bh = b*HH + h;
    const float* Q = qh + (size_t)bh*SQ*DD + (size_t)qt*64*DD;
    const float* K = kh + (size_t)bh*SQ*DD;
    const float* V = vh + (size_t)bh*SQ*DD;

    const int tid = threadIdx.x;
    const int tr = tid >> 3, tc = tid & 7;     // 8x8 thread grid
    const int r0 = tr*8, c0 = tc*8;

    // Load Q tile transposed (4096 floats, 16 float4 per thread)
    #pragma unroll
    for (int i = 0; i < 16; i++) {
        const int g = tid + 64*i;              // 0..1023
        const int row = g >> 4, c4 = (g & 15)*4;
        float4 v4 = *(const float4*)(Q + row*DD + c4);
        Qt[(c4+0)*64+row] = v4.x; Qt[(c4+1)*64+row] = v4.y;
        Qt[(c4+2)*64+row] = v4.z; Qt[(c4+3)*64+row] = v4.w;
    }

    float o[8][8];
    float m[8], l[8];
    #pragma unroll
    for (int i = 0; i < 8; i++) {
        m[i] = -CUDART_INF_F; l[i] = 0.f;
        #pragma unroll
        for (int j = 0; j < 8; j++) o[i][j] = 0.f;
    }
    const float slope = exp2f(-0.5f*(float)(h+1));

    for (int kt = 0; kt <= qt; kt++) {
        const float* Kp = K + (size_t)kt*64*DD;
        const float* Vp = V + (size_t)kt*64*DD;
        __syncthreads();   // previous PV reads done before overwrite
        #pragma unroll
        for (int i = 0; i < 16; i++) {
            const int g = tid + 64*i;
            const int row = g >> 4, c4 = (g & 15)*4;
            float4 kv = *(const float4*)(Kp + row*DD + c4);
            KPt[(c4+0)*64+row] = kv.x; KPt[(c4+1)*64+row] = kv.y;
            KPt[(c4+2)*64+row] = kv.z; KPt[(c4+3)*64+row] = kv.w;
            *(float4*)&Vs[row*64 + c4] = *(const float4*)(Vp + row*DD + c4);
        }
        __syncthreads();

        float s[8][8];
        #pragma unroll
        for (int i = 0; i < 8; i++)
            #pragma unroll
            for (int j = 0; j < 8; j++) s[i][j] = 0.f;

        #pragma unroll 4
        for (int d = 0; d < 64; d++) {
            float a[8], bb[8];
            *(float4*)(a)    = *(float4*)&Qt[d*64 + r0];
            *(float4*)(a+4)  = *(float4*)&Qt[d*64 + r0 + 4];
            *(float4*)(bb)   = *(float4*)&KPt[d*64 + c0];
            *(float4*)(bb+4) = *(float4*)&KPt[d*64 + c0 + 4];
            #pragma unroll
            for (int i = 0; i < 8; i++)
                #pragma unroll
                for (int j = 0; j < 8; j++)
                    s[i][j] += a[i]*bb[j];
        }

        const int qbase = qt*64 + r0, kbase = kt*64 + c0;
        #pragma unroll
        for (int i = 0; i < 8; i++) {
            #pragma unroll
            for (int j = 0; j < 8; j++) {
                const int qi = qbase + i, kj = kbase + j;
                if (kj > qi) s[i][j] = -CUDART_INF_F;
                else s[i][j] = s[i][j]*0.125f - slope*(float)(qi - kj);
            }
        }

        // online softmax per row (8 lanes share a row group: shfl 4,2,1)
        #pragma unroll
        for (int i = 0; i < 8; i++) {
            float mx = s[i][0];
            #pragma unroll
            for (int j = 1; j < 8; j++) mx = fmaxf(mx, s[i][j]);
            #pragma unroll
            for (int off = 4; off; off >>= 1)
                mx = fmaxf(mx, __shfl_xor_sync(0xffffffffu, mx, off));
            const float mnew = fmaxf(m[i], mx);
            const float alpha = __expf(m[i] - mnew);
            float rs = 0.f;
            #pragma unroll
            for (int j = 0; j < 8; j++) {
                const float p = __expf(s[i][j] - mnew);
                s[i][j] = p; rs += p;
            }
            #pragma unroll
            for (int off = 4; off; off >>= 1)
                rs += __shfl_xor_sync(0xffffffffu, rs, off);
            l[i] = l[i]*alpha + rs;
            m[i] = mnew;
            #pragma unroll
            for (int j = 0; j < 8; j++) o[i][j] *= alpha;
        }

        // K fully consumed -> overwrite KPt with P-transposed
        __syncthreads();
        #pragma unroll
        for (int j = 0; j < 8; j++)
            #pragma unroll
            for (int i = 0; i < 8; i++)
                KPt[(c0+j)*64 + (r0+i)] = s[i][j];
        __syncthreads();

        // O += P @ V
        #pragma unroll 4
        for (int jj = 0; jj < 64; jj++) {
            float p4[8], v4[8];
            *(float4*)(p4)   = *(float4*)&KPt[jj*64 + r0];
            *(float4*)(p4+4) = *(float4*)&KPt[jj*64 + r0 + 4];
            *(float4*)(v4)   = *(float4*)&Vs[jj*64 + c0];
            *(float4*)(v4+4) = *(float4*)&Vs[jj*64 + c0 + 4];
            #pragma unroll
            for (int i = 0; i < 8; i++)
                #pragma unroll
                for (int j = 0; j < 8; j++)
                    o[i][j] += p4[i]*v4[j];
        }
    }

    // normalize + store to [B,S,E] context buffer
    #pragma unroll
    for (int i = 0; i < 8; i++) {
        const float inv = 1.f / l[i];
        const int qi = qt*64 + r0 + i;
        float* outp = att + ((size_t)(b*SQ + qi))*EE + h*DD + c0;
        float4 w0, w1;
        w0.x = o[i][0]*inv; w0.y = o[i][1]*inv;
        w0.z = o[i][2]*inv; w0.w = o[i][3]*inv;
        w1.x = o[i][4]*inv; w1.y = o[i][5]*inv;
        w1.z = o[i][6]*inv; w1.w = o[i][7]*inv;
        *(float4*)(outp)     = w0;
        *(float4*)(outp + 4) = w1;
    }
}

// ---------------------------------------------------------------------------
// Head-0 attention probabilities (second output). One CTA per (query row, b).
// ---------------------------------------------------------------------------
__global__ __launch_bounds__(256) void attn0_kernel(
    const float* __restrict__ qh, const float* __restrict__ kh,
    float* __restrict__ attn_out)
{
    __shared__ float qrow[64];
    __shared__ float lg[SQ];
    __shared__ float redmax[8];
    __shared__ float redsum[8];

    const int i = (SQ - 1) - blockIdx.x;    // biggest rows first
    const int b = blockIdx.y;
    const float* Q = qh + ((size_t)(b*HH)*SQ + i)*DD;
    const float* K = kh + (size_t)(b*HH)*SQ*DD;
    const int tid = threadIdx.x;

    if (tid < 64) qrow[tid] = Q[tid];
    __syncthreads();

    const float slope = 0.70710678118654752f;  // 2^-0.5 (head 1 of 16)
    float lmax = -CUDART_INF_F;
    for (int j = tid; j <= i; j += 256) {
        const float4* kp = (const float4*)(K + (size_t)j*DD);
        float dot = 0.f;
        #pragma unroll
        for (int d4 = 0; d4 < 16; d4++) {
            float4 kv = kp[d4];
            float4 qv = *(const float4*)&qrow[d4*4];
            dot += kv.x*qv.x + kv.y*qv.y + kv.z*qv.z + kv.w*qv.w;
        }
        const float v = dot*0.125f - slope*(float)(i - j);
        lg[j] = v;
        lmax = fmaxf(lmax, v);
    }
    // block max
    #pragma unroll
    for (int off = 16; off; off >>= 1)
        lmax = fmaxf(lmax, __shfl_xor_sync(0xffffffffu, lmax, off));
    if ((tid & 31) == 0) redmax[tid >> 5] = lmax;
    __syncthreads();
    float gmax = redmax[0];
    #pragma unroll
    for (int w = 1; w < 8; w++) gmax = fmaxf(gmax, redmax[w]);

    float psum = 0.f;
    for (int j = tid; j <= i; j += 256) {
        const float p = __expf(lg[j] - gmax);
        lg[j] = p;
        psum += p;
    }
    #pragma unroll
    for (int off = 16; off; off >>= 1)
        psum += __shfl_xor_sync(0xffffffffu, psum, off);
    if ((tid & 31) == 0) redsum[tid >> 5] = psum;
    __syncthreads();
    float gsum = 0.f;
    #pragma unroll
    for (int w = 0; w < 8; w++) gsum += redsum[w];
    const float inv = 1.f / gsum;

    float* outp = attn_out + ((size_t)(b*SQ + i))*SQ;
    for (int j = tid; j < SQ; j += 256)
        outp[j] = (j <= i) ? lg[j]*inv : 0.f;
}

// ---------------------------------------------------------------------------
extern "C" void kernel_launch(void* const* d_in, const int* in_sizes, int n_in,
                              void* d_out, int out_size)
{
    const float* q  = (const float*)d_in[0];
    const float* k  = (const float*)d_in[1];
    const float* v  = (const float*)d_in[2];
    // d_in[3] = alibi, d_in[4] = mask  (computed analytically in-kernel)
    const float* wq = (const float*)d_in[5];
    const float* wk = (const float*)d_in[6];
    const float* wv = (const float*)d_in[7];
    const float* wd = (const float*)d_in[8];
    const float* bd = (const float*)d_in[9];

    float *qh, *kh, *vh, *att;
    cudaGetSymbolAddress((void**)&qh,  g_qh);
    cudaGetSymbolAddress((void**)&kh,  g_kh);
    cudaGetSymbolAddress((void**)&vh,  g_vh);
    cudaGetSymbolAddress((void**)&att, g_att);

    float* out_main = (float*)d_out;                       // [B,S,E]
    float* out_attn = (float*)d_out + (size_t)MM*EE;       // [B,S,S]

    const dim3 gemm_grid(EE/128, MM/128);   // 8 x 32

    gemm_nt<<<gemm_grid, 256>>>(q, wq, nullptr, qh, MM, EE, EE, 1);
    gemm_nt<<<gemm_grid, 256>>>(k, wk, nullptr, kh, MM, EE, EE, 1);
    gemm_nt<<<gemm_grid, 256>>>(v, wv, nullptr, vh, MM, EE, EE, 1);

    flash_kernel<<<dim3(SQ/64, HH, BB), 64>>>(qh, kh, vh, att);

    attn0_kernel<<<dim3(SQ, BB), 256>>>(qh, kh, out_attn);

    gemm_nt<<<gemm_grid, 256>>>(att, wd, bd, out_main, MM, EE, EE, 0);
}

// round 6
// speedup vs baseline: 1.4848x; 1.4848x over previous
#include <cuda_runtime.h>
#include <cuda_bf16.h>
#include <math_constants.h>
#include <cstdint>

// Problem constants
#define BB 2
#define SQ 2048
#define EE 1024
#define HH 16
#define DD 64
#define MM (BB*SQ)   // 4096 rows

// Scratch (device globals: allocation-free rule)
__device__ float g_qh[BB*HH*SQ*DD];   // [B,H,S,D]
__device__ float g_kh[BB*HH*SQ*DD];
__device__ float g_vh[BB*HH*SQ*DD];
__device__ float g_att[BB*SQ*EE];     // attention context in [B,S,E]

// ---------------------------------------------------------------------------
// Tensor-core GEMM: C = A(MxK) @ W(NxK)^T (+bias), bf16 3-mma split for
// ~fp32 accuracy. 128x128x16 tiles, 8 warps (each 64x32), double-buffered.
// headmode=1 scatters to [B,H,S,D].
// ---------------------------------------------------------------------------
#define MMA_BF16(cc, A0, A1, A2, A3, B0, B1)                                  \
    asm volatile("mma.sync.aligned.m16n8k16.row.col.f32.bf16.bf16.f32 "       \
                 "{%0,%1,%2,%3}, {%4,%5,%6,%7}, {%8,%9}, {%0,%1,%2,%3};"      \
                 : "+f"(cc[0]), "+f"(cc[1]), "+f"(cc[2]), "+f"(cc[3])         \
                 : "r"(A0), "r"(A1), "r"(A2), "r"(A3), "r"(B0), "r"(B1))

__device__ __forceinline__ uint32_t pack_bf16(__nv_bfloat16 lo16, __nv_bfloat16 hi16) {
    return (uint32_t)__bfloat16_as_ushort(lo16) |
           ((uint32_t)__bfloat16_as_ushort(hi16) << 16);
}

// Split a float4 (4 consecutive k) into bf16 hi/lo and store packed pairs.
__device__ __forceinline__ void split_store(
    unsigned short (*Hs)[24], unsigned short (*Ls)[24],
    int row, int kcol, float4 v)
{
    __nv_bfloat16 h0 = __float2bfloat16(v.x), h1 = __float2bfloat16(v.y),
                  h2 = __float2bfloat16(v.z), h3 = __float2bfloat16(v.w);
    __nv_bfloat16 l0 = __float2bfloat16(v.x - __bfloat162float(h0));
    __nv_bfloat16 l1 = __float2bfloat16(v.y - __bfloat162float(h1));
    __nv_bfloat16 l2 = __float2bfloat16(v.z - __bfloat162float(h2));
    __nv_bfloat16 l3 = __float2bfloat16(v.w - __bfloat162float(h3));
    *(uint32_t*)&Hs[row][kcol]     = pack_bf16(h0, h1);
    *(uint32_t*)&Hs[row][kcol + 2] = pack_bf16(h2, h3);
    *(uint32_t*)&Ls[row][kcol]     = pack_bf16(l0, l1);
    *(uint32_t*)&Ls[row][kcol + 2] = pack_bf16(l2, l3);
}

__global__ __launch_bounds__(256, 2) void gemm_bf16x3(
    const float* __restrict__ A, const float* __restrict__ W,
    const float* __restrict__ bias, float* __restrict__ C,
    int M, int N, int K, int headmode)
{
    // 2 stages x 128 rows x (16 k-halves + 8 pad) -> 48KB total (4 arrays)
    __shared__ unsigned short Ah[2][128][24];
    __shared__ unsigned short Al[2][128][24];
    __shared__ unsigned short Bh[2][128][24];
    __shared__ unsigned short Bl[2][128][24];

    const int m0 = blockIdx.y * 128;
    const int n0 = blockIdx.x * 128;
    const int tid  = threadIdx.x;
    const int wid  = tid >> 5, lane = tid & 31;
    const int g    = lane >> 2, tig = lane & 3;
    const int wr   = (wid >> 2) * 64;     // warp row (2 rows of warps)
    const int wc   = (wid & 3) * 32;      // warp col (4 cols of warps)

    // Fill assignment: each thread loads rows fm and fm+64, k-quad fk.
    const int fm = tid >> 2;              // 0..63
    const int fk = (tid & 3) * 4;         // 0,4,8,12
    const float* Ap0 = A + (size_t)(m0 + fm)      * K + fk;
    const float* Ap1 = A + (size_t)(m0 + fm + 64) * K + fk;
    const float* Wp0 = W + (size_t)(n0 + fm)      * K + fk;
    const float* Wp1 = W + (size_t)(n0 + fm + 64) * K + fk;

    float c[4][4][4];
    #pragma unroll
    for (int mf = 0; mf < 4; mf++)
        #pragma unroll
        for (int nf = 0; nf < 4; nf++)
            #pragma unroll
            for (int r = 0; r < 4; r++) c[mf][nf][r] = 0.f;

    // Prologue: stage 0
    {
        float4 a0 = *(const float4*)Ap0;
        float4 a1 = *(const float4*)Ap1;
        float4 w0 = *(const float4*)Wp0;
        float4 w1 = *(const float4*)Wp1;
        split_store(Ah[0], Al[0], fm,      fk, a0);
        split_store(Ah[0], Al[0], fm + 64, fk, a1);
        split_store(Bh[0], Bl[0], fm,      fk, w0);
        split_store(Bh[0], Bl[0], fm + 64, fk, w1);
    }
    __syncthreads();

    const int NT = K / 16;
    int cur = 0;
    for (int kt = 0; kt < NT; kt++) {
        float4 pa0, pa1, pw0, pw1;
        const bool more = (kt + 1) < NT;
        if (more) {
            const int ko = (kt + 1) * 16;
            pa0 = *(const float4*)(Ap0 + ko);
            pa1 = *(const float4*)(Ap1 + ko);
            pw0 = *(const float4*)(Wp0 + ko);
            pw1 = *(const float4*)(Wp1 + ko);
        }

        // --- fragments from stage cur ---
        uint32_t a[4][4], bhr[4][2], blr[4][2];
        #pragma unroll
        for (int mf = 0; mf < 4; mf++) {
            const int rb = wr + mf * 16;
            a[mf][0] = *(const uint32_t*)&Ah[cur][rb + g    ][2 * tig];
            a[mf][1] = *(const uint32_t*)&Ah[cur][rb + 8 + g][2 * tig];
            a[mf][2] = *(const uint32_t*)&Ah[cur][rb + g    ][2 * tig + 8];
            a[mf][3] = *(const uint32_t*)&Ah[cur][rb + 8 + g][2 * tig + 8];
        }
        #pragma unroll
        for (int nf = 0; nf < 4; nf++) {
            const int cb = wc + nf * 8;
            bhr[nf][0] = *(const uint32_t*)&Bh[cur][cb + g][2 * tig];
            bhr[nf][1] = *(const uint32_t*)&Bh[cur][cb + g][2 * tig + 8];
            blr[nf][0] = *(const uint32_t*)&Bl[cur][cb + g][2 * tig];
            blr[nf][1] = *(const uint32_t*)&Bl[cur][cb + g][2 * tig + 8];
        }
        // hi*hi and hi*lo
        #pragma unroll
        for (int mf = 0; mf < 4; mf++)
            #pragma unroll
            for (int nf = 0; nf < 4; nf++) {
                MMA_BF16(c[mf][nf], a[mf][0], a[mf][1], a[mf][2], a[mf][3],
                         bhr[nf][0], bhr[nf][1]);
                MMA_BF16(c[mf][nf], a[mf][0], a[mf][1], a[mf][2], a[mf][3],
                         blr[nf][0], blr[nf][1]);
            }
        // lo*hi (reload A frags from Al, reusing registers)
        #pragma unroll
        for (int mf = 0; mf < 4; mf++) {
            const int rb = wr + mf * 16;
            a[mf][0] = *(const uint32_t*)&Al[cur][rb + g    ][2 * tig];
            a[mf][1] = *(const uint32_t*)&Al[cur][rb + 8 + g][2 * tig];
            a[mf][2] = *(const uint32_t*)&Al[cur][rb + g    ][2 * tig + 8];
            a[mf][3] = *(const uint32_t*)&Al[cur][rb + 8 + g][2 * tig + 8];
        }
        #pragma unroll
        for (int mf = 0; mf < 4; mf++)
            #pragma unroll
            for (int nf = 0; nf < 4; nf++)
                MMA_BF16(c[mf][nf], a[mf][0], a[mf][1], a[mf][2], a[mf][3],
                         bhr[nf][0], bhr[nf][1]);

        if (more) {
            const int nxt = cur ^ 1;
            split_store(Ah[nxt], Al[nxt], fm,      fk, pa0);
            split_store(Ah[nxt], Al[nxt], fm + 64, fk, pa1);
            split_store(Bh[nxt], Bl[nxt], fm,      fk, pw0);
            split_store(Bh[nxt], Bl[nxt], fm + 64, fk, pw1);
        }
        __syncthreads();
        cur ^= 1;
    }

    // Epilogue: c0,c1 -> (row, col..col+1), c2,c3 -> (row+8, col..col+1)
    #pragma unroll
    for (int mf = 0; mf < 4; mf++) {
        #pragma unroll
        for (int nf = 0; nf < 4; nf++) {
            const int r  = m0 + wr + mf * 16 + g;
            const int cc = n0 + wc + nf * 8 + 2 * tig;
            float v0 = c[mf][nf][0], v1 = c[mf][nf][1];
            float v2 = c[mf][nf][2], v3 = c[mf][nf][3];
            if (bias) {
                const float b0 = bias[cc], b1 = bias[cc + 1];
                v0 += b0; v1 += b1; v2 += b0; v3 += b1;
            }
            if (headmode) {
                const int b  = r >> 11, s  = r & 2047;
                const int h  = cc >> 6, d  = cc & 63;
                float* p0 = C + (((size_t)(b * HH + h) * SQ + s) * DD + d);
                *(float2*)p0 = make_float2(v0, v1);
                const int rb2 = r + 8;
                const int bb2 = rb2 >> 11, ss2 = rb2 & 2047;
                float* p1 = C + (((size_t)(bb2 * HH + h) * SQ + ss2) * DD + d);
                *(float2*)p1 = make_float2(v2, v3);
            } else {
                *(float2*)(C + (size_t)r * N + cc)       = make_float2(v0, v1);
                *(float2*)(C + (size_t)(r + 8) * N + cc) = make_float2(v2, v3);
            }
        }
    }
}

// ---------------------------------------------------------------------------
// Flash attention (causal + ALiBi), fp32. One CTA = (64 q-rows, one b,h).
// 64 threads as 8x8 grid, 8x8 micro-tiles. Static smem 48KB;
// K-transposed and P-transposed alias one buffer.  (R4-measured: 955us)
// ---------------------------------------------------------------------------
__global__ __launch_bounds__(64, 4) void flash_kernel(
    const float* __restrict__ qh, const float* __restrict__ kh,
    const float* __restrict__ vh, float* __restrict__ att)
{
    __shared__ float Qt[64*64];    // [d][q]
    __shared__ float KPt[64*64];   // [d][c] for K, then [j][r] for P
    __shared__ float Vs[64*64];    // [j][c]

    const int qt = (SQ/64 - 1) - blockIdx.x;   // biggest tiles first
    const int h  = blockIdx.y;
    const int b  = blockIdx.z;
    const int bh = b*HH + h;
    const float* Q = qh + (size_t)bh*SQ*DD + (size_t)qt*64*DD;
    const float* K = kh + (size_t)bh*SQ*DD;
    const float* V = vh + (size_t)bh*SQ*DD;

    const int tid = threadIdx.x;
    const int tr = tid >> 3, tc = tid & 7;     // 8x8 thread grid
    const int r0 = tr*8, c0 = tc*8;

    // Load Q tile transposed (4096 floats, 16 float4 per thread)
    #pragma unroll
    for (int i = 0; i < 16; i++) {
        const int g = tid + 64*i;              // 0..1023
        const int row = g >> 4, c4 = (g & 15)*4;
        float4 v4 = *(const float4*)(Q + row*DD + c4);
        Qt[(c4+0)*64+row] = v4.x; Qt[(c4+1)*64+row] = v4.y;
        Qt[(c4+2)*64+row] = v4.z; Qt[(c4+3)*64+row] = v4.w;
    }

    float o[8][8];
    float m[8], l[8];
    #pragma unroll
    for (int i = 0; i < 8; i++) {
        m[i] = -CUDART_INF_F; l[i] = 0.f;
        #pragma unroll
        for (int j = 0; j < 8; j++) o[i][j] = 0.f;
    }
    const float slope = exp2f(-0.5f*(float)(h+1));

    for (int kt = 0; kt <= qt; kt++) {
        const float* Kp = K + (size_t)kt*64*DD;
        const float* Vp = V + (size_t)kt*64*DD;
        __syncthreads();   // previous PV reads done before overwrite
        #pragma unroll
        for (int i = 0; i < 16; i++) {
            const int g = tid + 64*i;
            const int row = g >> 4, c4 = (g & 15)*4;
            float4 kv = *(const float4*)(Kp + row*DD + c4);
            KPt[(c4+0)*64+row] = kv.x; KPt[(c4+1)*64+row] = kv.y;
            KPt[(c4+2)*64+row] = kv.z; KPt[(c4+3)*64+row] = kv.w;
            *(float4*)&Vs[row*64 + c4] = *(const float4*)(Vp + row*DD + c4);
        }
        __syncthreads();

        float s[8][8];
        #pragma unroll
        for (int i = 0; i < 8; i++)
            #pragma unroll
            for (int j = 0; j < 8; j++) s[i][j] = 0.f;

        #pragma unroll 4
        for (int d = 0; d < 64; d++) {
            float a[8], bb[8];
            *(float4*)(a)    = *(float4*)&Qt[d*64 + r0];
            *(float4*)(a+4)  = *(float4*)&Qt[d*64 + r0 + 4];
            *(float4*)(bb)   = *(float4*)&KPt[d*64 + c0];
            *(float4*)(bb+4) = *(float4*)&KPt[d*64 + c0 + 4];
            #pragma unroll
            for (int i = 0; i < 8; i++)
                #pragma unroll
                for (int j = 0; j < 8; j++)
                    s[i][j] += a[i]*bb[j];
        }

        const int qbase = qt*64 + r0, kbase = kt*64 + c0;
        #pragma unroll
        for (int i = 0; i < 8; i++) {
            #pragma unroll
            for (int j = 0; j < 8; j++) {
                const int qi = qbase + i, kj = kbase + j;
                if (kj > qi) s[i][j] = -CUDART_INF_F;
                else s[i][j] = s[i][j]*0.125f - slope*(float)(qi - kj);
            }
        }

        // online softmax per row (8 lanes share a row group: shfl 4,2,1)
        #pragma unroll
        for (int i = 0; i < 8; i++) {
            float mx = s[i][0];
            #pragma unroll
            for (int j = 1; j < 8; j++) mx = fmaxf(mx, s[i][j]);
            #pragma unroll
            for (int off = 4; off; off >>= 1)
                mx = fmaxf(mx, __shfl_xor_sync(0xffffffffu, mx, off));
            const float mnew = fmaxf(m[i], mx);
            const float alpha = __expf(m[i] - mnew);
            float rs = 0.f;
            #pragma unroll
            for (int j = 0; j < 8; j++) {
                const float p = __expf(s[i][j] - mnew);
                s[i][j] = p; rs += p;
            }
            #pragma unroll
            for (int off = 4; off; off >>= 1)
                rs += __shfl_xor_sync(0xffffffffu, rs, off);
            l[i] = l[i]*alpha + rs;
            m[i] = mnew;
            #pragma unroll
            for (int j = 0; j < 8; j++) o[i][j] *= alpha;
        }

        // K fully consumed -> overwrite KPt with P-transposed
        __syncthreads();
        #pragma unroll
        for (int j = 0; j < 8; j++)
            #pragma unroll
            for (int i = 0; i < 8; i++)
                KPt[(c0+j)*64 + (r0+i)] = s[i][j];
        __syncthreads();

        // O += P @ V
        #pragma unroll 4
        for (int jj = 0; jj < 64; jj++) {
            float p4[8], v4[8];
            *(float4*)(p4)   = *(float4*)&KPt[jj*64 + r0];
            *(float4*)(p4+4) = *(float4*)&KPt[jj*64 + r0 + 4];
            *(float4*)(v4)   = *(float4*)&Vs[jj*64 + c0];
            *(float4*)(v4+4) = *(float4*)&Vs[jj*64 + c0 + 4];
            #pragma unroll
            for (int i = 0; i < 8; i++)
                #pragma unroll
                for (int j = 0; j < 8; j++)
                    o[i][j] += p4[i]*v4[j];
        }
    }

    // normalize + store to [B,S,E] context buffer
    #pragma unroll
    for (int i = 0; i < 8; i++) {
        const float inv = 1.f / l[i];
        const int qi = qt*64 + r0 + i;
        float* outp = att + ((size_t)(b*SQ + qi))*EE + h*DD + c0;
        float4 w0, w1;
        w0.x = o[i][0]*inv; w0.y = o[i][1]*inv;
        w0.z = o[i][2]*inv; w0.w = o[i][3]*inv;
        w1.x = o[i][4]*inv; w1.y = o[i][5]*inv;
        w1.z = o[i][6]*inv; w1.w = o[i][7]*inv;
        *(float4*)(outp)     = w0;
        *(float4*)(outp + 4) = w1;
    }
}

// ---------------------------------------------------------------------------
// Head-0 attention probabilities (second output). One CTA per (query row, b).
// ---------------------------------------------------------------------------
__global__ __launch_bounds__(256) void attn0_kernel(
    const float* __restrict__ qh, const float* __restrict__ kh,
    float* __restrict__ attn_out)
{
    __shared__ float qrow[64];
    __shared__ float lg[SQ];
    __shared__ float redmax[8];
    __shared__ float redsum[8];

    const int i = (SQ - 1) - blockIdx.x;    // biggest rows first
    const int b = blockIdx.y;
    const float* Q = qh + ((size_t)(b*HH)*SQ + i)*DD;
    const float* K = kh + (size_t)(b*HH)*SQ*DD;
    const int tid = threadIdx.x;

    if (tid < 64) qrow[tid] = Q[tid];
    __syncthreads();

    const float slope = 0.70710678118654752f;  // 2^-0.5 (head 1 of 16)
    float lmax = -CUDART_INF_F;
    for (int j = tid; j <= i; j += 256) {
        const float4* kp = (const float4*)(K + (size_t)j*DD);
        float dot = 0.f;
        #pragma unroll
        for (int d4 = 0; d4 < 16; d4++) {
            float4 kv = kp[d4];
            float4 qv = *(const float4*)&qrow[d4*4];
            dot += kv.x*qv.x + kv.y*qv.y + kv.z*qv.z + kv.w*qv.w;
        }
        const float v = dot*0.125f - slope*(float)(i - j);
        lg[j] = v;
        lmax = fmaxf(lmax, v);
    }
    // block max
    #pragma unroll
    for (int off = 16; off; off >>= 1)
        lmax = fmaxf(lmax, __shfl_xor_sync(0xffffffffu, lmax, off));
    if ((tid & 31) == 0) redmax[tid >> 5] = lmax;
    __syncthreads();
    float gmax = redmax[0];
    #pragma unroll
    for (int w = 1; w < 8; w++) gmax = fmaxf(gmax, redmax[w]);

    float psum = 0.f;
    for (int j = tid; j <= i; j += 256) {
        const float p = __expf(lg[j] - gmax);
        lg[j] = p;
        psum += p;
    }
    #pragma unroll
    for (int off = 16; off; off >>= 1)
        psum += __shfl_xor_sync(0xffffffffu, psum, off);
    if ((tid & 31) == 0) redsum[tid >> 5] = psum;
    __syncthreads();
    float gsum = 0.f;
    #pragma unroll
    for (int w = 0; w < 8; w++) gsum += redsum[w];
    const float inv = 1.f / gsum;

    float* outp = attn_out + ((size_t)(b*SQ + i))*SQ;
    for (int j = tid; j < SQ; j += 256)
        outp[j] = (j <= i) ? lg[j]*inv : 0.f;
}

// ---------------------------------------------------------------------------
extern "C" void kernel_launch(void* const* d_in, const int* in_sizes, int n_in,
                              void* d_out, int out_size)
{
    const float* q  = (const float*)d_in[0];
    const float* k  = (const float*)d_in[1];
    const float* v  = (const float*)d_in[2];
    // d_in[3] = alibi, d_in[4] = mask  (computed analytically in-kernel)
    const float* wq = (const float*)d_in[5];
    const float* wk = (const float*)d_in[6];
    const float* wv = (const float*)d_in[7];
    const float* wd = (const float*)d_in[8];
    const float* bd = (const float*)d_in[9];

    float *qh, *kh, *vh, *att;
    cudaGetSymbolAddress((void**)&qh,  g_qh);
    cudaGetSymbolAddress((void**)&kh,  g_kh);
    cudaGetSymbolAddress((void**)&vh,  g_vh);
    cudaGetSymbolAddress((void**)&att, g_att);

    float* out_main = (float*)d_out;                       // [B,S,E]
    float* out_attn = (float*)d_out + (size_t)MM*EE;       // [B,S,S]

    const dim3 gemm_grid(EE/128, MM/128);   // 8 x 32

    gemm_bf16x3<<<gemm_grid, 256>>>(q, wq, nullptr, qh, MM, EE, EE, 1);
    gemm_bf16x3<<<gemm_grid, 256>>>(k, wk, nullptr, kh, MM, EE, EE, 1);
    gemm_bf16x3<<<gemm_grid, 256>>>(v, wv, nullptr, vh, MM, EE, EE, 1);

    flash_kernel<<<dim3(SQ/64, HH, BB), 64>>>(qh, kh, vh, att);

    attn0_kernel<<<dim3(SQ, BB), 256>>>(qh, kh, out_attn);

    gemm_bf16x3<<<gemm_grid, 256>>>(att, wd, bd, out_main, MM, EE, EE, 0);
}

// round 7
// speedup vs baseline: 2.2394x; 1.5082x over previous
#include <cuda_runtime.h>
#include <cuda_bf16.h>
#include <math_constants.h>
#include <cstdint>

// Problem constants
#define BB 2
#define SQ 2048
#define EE 1024
#define HH 16
#define DD 64
#define MM (BB*SQ)   // 4096 rows

// Scratch (device globals: allocation-free rule)
__device__ float g_qh[BB*HH*SQ*DD];   // [B,H,S,D]
__device__ float g_kh[BB*HH*SQ*DD];
__device__ float g_vh[BB*HH*SQ*DD];
__device__ float g_att[BB*SQ*EE];     // attention context in [B,S,E]

#define MMA_BF16(cc, A0, A1, A2, A3, B0, B1)                                  \
    asm volatile("mma.sync.aligned.m16n8k16.row.col.f32.bf16.bf16.f32 "       \
                 "{%0,%1,%2,%3}, {%4,%5,%6,%7}, {%8,%9}, {%0,%1,%2,%3};"      \
                 : "+f"(cc[0]), "+f"(cc[1]), "+f"(cc[2]), "+f"(cc[3])         \
                 : "r"(A0), "r"(A1), "r"(A2), "r"(A3), "r"(B0), "r"(B1))

__device__ __forceinline__ uint32_t pack_bf16(__nv_bfloat16 lo16, __nv_bfloat16 hi16) {
    return (uint32_t)__bfloat16_as_ushort(lo16) |
           ((uint32_t)__bfloat16_as_ushort(hi16) << 16);
}

// Split two floats into packed bf16 hi and lo words (lo half = first arg).
__device__ __forceinline__ void split2(float a, float b, uint32_t& hi, uint32_t& lo) {
    __nv_bfloat16 ha = __float2bfloat16(a), hb = __float2bfloat16(b);
    __nv_bfloat16 la = __float2bfloat16(a - __bfloat162float(ha));
    __nv_bfloat16 lb = __float2bfloat16(b - __bfloat162float(hb));
    hi = pack_bf16(ha, hb);
    lo = pack_bf16(la, lb);
}

// Convert a float4 row segment to bf16 hi/lo at hp/lp (4 consecutive halves).
__device__ __forceinline__ void cvt_row4(unsigned short* hp, unsigned short* lp, float4 v) {
    uint32_t h01, l01, h23, l23;
    split2(v.x, v.y, h01, l01);
    split2(v.z, v.w, h23, l23);
    *(uint32_t*)hp       = h01; *(uint32_t*)(hp + 2) = h23;
    *(uint32_t*)lp       = l01; *(uint32_t*)(lp + 2) = l23;
}

// ---------------------------------------------------------------------------
// Tensor-core GEMM: C = A(MxK) @ W(NxK)^T (+bias), bf16 3-mma split.
// 128x128x16 tiles, 8 warps, double-buffered. (R6-measured)
// ---------------------------------------------------------------------------
__device__ __forceinline__ void split_store(
    unsigned short (*Hs)[24], unsigned short (*Ls)[24],
    int row, int kcol, float4 v)
{
    cvt_row4(&Hs[row][kcol], &Ls[row][kcol], v);
}

__global__ __launch_bounds__(256, 2) void gemm_bf16x3(
    const float* __restrict__ A, const float* __restrict__ W,
    const float* __restrict__ bias, float* __restrict__ C,
    int M, int N, int K, int headmode)
{
    __shared__ unsigned short Ah[2][128][24];
    __shared__ unsigned short Al[2][128][24];
    __shared__ unsigned short Bh[2][128][24];
    __shared__ unsigned short Bl[2][128][24];

    const int m0 = blockIdx.y * 128;
    const int n0 = blockIdx.x * 128;
    const int tid  = threadIdx.x;
    const int wid  = tid >> 5, lane = tid & 31;
    const int g    = lane >> 2, tig = lane & 3;
    const int wr   = (wid >> 2) * 64;
    const int wc   = (wid & 3) * 32;

    const int fm = tid >> 2;
    const int fk = (tid & 3) * 4;
    const float* Ap0 = A + (size_t)(m0 + fm)      * K + fk;
    const float* Ap1 = A + (size_t)(m0 + fm + 64) * K + fk;
    const float* Wp0 = W + (size_t)(n0 + fm)      * K + fk;
    const float* Wp1 = W + (size_t)(n0 + fm + 64) * K + fk;

    float c[4][4][4];
    #pragma unroll
    for (int mf = 0; mf < 4; mf++)
        #pragma unroll
        for (int nf = 0; nf < 4; nf++)
            #pragma unroll
            for (int r = 0; r < 4; r++) c[mf][nf][r] = 0.f;

    {
        split_store(Ah[0], Al[0], fm,      fk, *(const float4*)Ap0);
        split_store(Ah[0], Al[0], fm + 64, fk, *(const float4*)Ap1);
        split_store(Bh[0], Bl[0], fm,      fk, *(const float4*)Wp0);
        split_store(Bh[0], Bl[0], fm + 64, fk, *(const float4*)Wp1);
    }
    __syncthreads();

    const int NT = K / 16;
    int cur = 0;
    for (int kt = 0; kt < NT; kt++) {
        float4 pa0, pa1, pw0, pw1;
        const bool more = (kt + 1) < NT;
        if (more) {
            const int ko = (kt + 1) * 16;
            pa0 = *(const float4*)(Ap0 + ko);
            pa1 = *(const float4*)(Ap1 + ko);
            pw0 = *(const float4*)(Wp0 + ko);
            pw1 = *(const float4*)(Wp1 + ko);
        }

        uint32_t a[4][4], bhr[4][2], blr[4][2];
        #pragma unroll
        for (int mf = 0; mf < 4; mf++) {
            const int rb = wr + mf * 16;
            a[mf][0] = *(const uint32_t*)&Ah[cur][rb + g    ][2 * tig];
            a[mf][1] = *(const uint32_t*)&Ah[cur][rb + 8 + g][2 * tig];
            a[mf][2] = *(const uint32_t*)&Ah[cur][rb + g    ][2 * tig + 8];
            a[mf][3] = *(const uint32_t*)&Ah[cur][rb + 8 + g][2 * tig + 8];
        }
        #pragma unroll
        for (int nf = 0; nf < 4; nf++) {
            const int cb = wc + nf * 8;
            bhr[nf][0] = *(const uint32_t*)&Bh[cur][cb + g][2 * tig];
            bhr[nf][1] = *(const uint32_t*)&Bh[cur][cb + g][2 * tig + 8];
            blr[nf][0] = *(const uint32_t*)&Bl[cur][cb + g][2 * tig];
            blr[nf][1] = *(const uint32_t*)&Bl[cur][cb + g][2 * tig + 8];
        }
        #pragma unroll
        for (int mf = 0; mf < 4; mf++)
            #pragma unroll
            for (int nf = 0; nf < 4; nf++) {
                MMA_BF16(c[mf][nf], a[mf][0], a[mf][1], a[mf][2], a[mf][3],
                         bhr[nf][0], bhr[nf][1]);
                MMA_BF16(c[mf][nf], a[mf][0], a[mf][1], a[mf][2], a[mf][3],
                         blr[nf][0], blr[nf][1]);
            }
        #pragma unroll
        for (int mf = 0; mf < 4; mf++) {
            const int rb = wr + mf * 16;
            a[mf][0] = *(const uint32_t*)&Al[cur][rb + g    ][2 * tig];
            a[mf][1] = *(const uint32_t*)&Al[cur][rb + 8 + g][2 * tig];
            a[mf][2] = *(const uint32_t*)&Al[cur][rb + g    ][2 * tig + 8];
            a[mf][3] = *(const uint32_t*)&Al[cur][rb + 8 + g][2 * tig + 8];
        }
        #pragma unroll
        for (int mf = 0; mf < 4; mf++)
            #pragma unroll
            for (int nf = 0; nf < 4; nf++)
                MMA_BF16(c[mf][nf], a[mf][0], a[mf][1], a[mf][2], a[mf][3],
                         bhr[nf][0], bhr[nf][1]);

        if (more) {
            const int nxt = cur ^ 1;
            split_store(Ah[nxt], Al[nxt], fm,      fk, pa0);
            split_store(Ah[nxt], Al[nxt], fm + 64, fk, pa1);
            split_store(Bh[nxt], Bl[nxt], fm,      fk, pw0);
            split_store(Bh[nxt], Bl[nxt], fm + 64, fk, pw1);
        }
        __syncthreads();
        cur ^= 1;
    }

    #pragma unroll
    for (int mf = 0; mf < 4; mf++) {
        #pragma unroll
        for (int nf = 0; nf < 4; nf++) {
            const int r  = m0 + wr + mf * 16 + g;
            const int cc = n0 + wc + nf * 8 + 2 * tig;
            float v0 = c[mf][nf][0], v1 = c[mf][nf][1];
            float v2 = c[mf][nf][2], v3 = c[mf][nf][3];
            if (bias) {
                const float b0 = bias[cc], b1 = bias[cc + 1];
                v0 += b0; v1 += b1; v2 += b0; v3 += b1;
            }
            if (headmode) {
                const int b  = r >> 11, s  = r & 2047;
                const int h  = cc >> 6, d  = cc & 63;
                float* p0 = C + (((size_t)(b * HH + h) * SQ + s) * DD + d);
                *(float2*)p0 = make_float2(v0, v1);
                const int rb2 = r + 8;
                const int bb2 = rb2 >> 11, ss2 = rb2 & 2047;
                float* p1 = C + (((size_t)(bb2 * HH + h) * SQ + ss2) * DD + d);
                *(float2*)p1 = make_float2(v2, v3);
            } else {
                *(float2*)(C + (size_t)r * N + cc)       = make_float2(v0, v1);
                *(float2*)(C + (size_t)(r + 8) * N + cc) = make_float2(v2, v3);
            }
        }
    }
}

// ---------------------------------------------------------------------------
// Tensor-core flash attention (causal + ALiBi). CTA = 64 q-rows, one (b,h).
// 128 threads (4 warps x 16 q-rows). bf16 3-mma split for QK^T and PV.
// Dynamic smem 55296B: Qh/Ql [q][d], Kh/Kl [kcol][d], Vh/Vl [d][kcol],
// each 64x72 halves (72-half stride -> conflict-free fragment LDS).
// ---------------------------------------------------------------------------
__global__ __launch_bounds__(128) void flash_mma(
    const float* __restrict__ qh, const float* __restrict__ kh,
    const float* __restrict__ vh, float* __restrict__ att)
{
    extern __shared__ unsigned short fsm[];
    typedef unsigned short (*arr72)[72];
    arr72 Qh = (arr72)(fsm);
    arr72 Ql = (arr72)(fsm + 4608);
    arr72 Kh = (arr72)(fsm + 9216);
    arr72 Kl = (arr72)(fsm + 13824);
    arr72 Vh = (arr72)(fsm + 18432);
    arr72 Vl = (arr72)(fsm + 23040);

    const int qt = (SQ/64 - 1) - blockIdx.x;   // biggest tiles first
    const int h  = blockIdx.y;
    const int b  = blockIdx.z;
    const int bh = b*HH + h;
    const float* Qg = qh + (size_t)bh*SQ*DD + (size_t)qt*64*DD;
    const float* Kg = kh + (size_t)bh*SQ*DD;
    const float* Vg = vh + (size_t)bh*SQ*DD;

    const int tid  = threadIdx.x;
    const int wid  = tid >> 5, lane = tid & 31;
    const int g    = lane >> 2, t = lane & 3;
    const int wr   = wid * 16;

    // Load Q tile (64x64 fp32 -> hi/lo bf16)
    #pragma unroll
    for (int i = 0; i < 8; i++) {
        const int idx = tid + 128*i;           // 1024 float4 units
        const int row = idx >> 4, c4 = (idx & 15)*4;
        float4 v = *(const float4*)(Qg + (size_t)row*DD + c4);
        cvt_row4(&Qh[row][c4], &Ql[row][c4], v);
    }

    float o[8][4];
    float m[2], l[2];
    #pragma unroll
    for (int dn = 0; dn < 8; dn++)
        #pragma unroll
        for (int r = 0; r < 4; r++) o[dn][r] = 0.f;
    m[0] = m[1] = -CUDART_INF_F;
    l[0] = l[1] = 0.f;

    const float slope = exp2f(-0.5f*(float)(h+1));
    const int row0 = qt*64 + wr + g;           // global q row for c0/c1
    const int row1 = row0 + 8;                 // for c2/c3

    for (int kt = 0; kt <= qt; kt++) {
        __syncthreads();   // prior PV reads complete before overwrite
        // Load K (row-major) and V (transposed) tiles, hi/lo split
        #pragma unroll
        for (int i = 0; i < 8; i++) {
            const int idx = tid + 128*i;
            const int row = idx >> 4, c4 = (idx & 15)*4;
            float4 kv = *(const float4*)(Kg + (size_t)(kt*64+row)*DD + c4);
            cvt_row4(&Kh[row][c4], &Kl[row][c4], kv);
            float4 vv = *(const float4*)(Vg + (size_t)(kt*64+row)*DD + c4);
            float vals[4] = {vv.x, vv.y, vv.z, vv.w};
            #pragma unroll
            for (int e = 0; e < 4; e++) {
                __nv_bfloat16 hh2 = __float2bfloat16(vals[e]);
                __nv_bfloat16 ll2 = __float2bfloat16(vals[e] - __bfloat162float(hh2));
                Vh[c4+e][row] = __bfloat16_as_ushort(hh2);
                Vl[c4+e][row] = __bfloat16_as_ushort(ll2);
            }
        }
        __syncthreads();

        // S = Q @ K^T  (3-mma split)
        float s[8][4];
        #pragma unroll
        for (int nf = 0; nf < 8; nf++)
            #pragma unroll
            for (int r = 0; r < 4; r++) s[nf][r] = 0.f;

        #pragma unroll
        for (int ks = 0; ks < 4; ks++) {
            const int kb = ks*16 + 2*t;
            uint32_t ah[4], al[4];
            ah[0] = *(const uint32_t*)&Qh[wr + g    ][kb];
            ah[1] = *(const uint32_t*)&Qh[wr + 8 + g][kb];
            ah[2] = *(const uint32_t*)&Qh[wr + g    ][kb + 8];
            ah[3] = *(const uint32_t*)&Qh[wr + 8 + g][kb + 8];
            al[0] = *(const uint32_t*)&Ql[wr + g    ][kb];
            al[1] = *(const uint32_t*)&Ql[wr + 8 + g][kb];
            al[2] = *(const uint32_t*)&Ql[wr + g    ][kb + 8];
            al[3] = *(const uint32_t*)&Ql[wr + 8 + g][kb + 8];
            #pragma unroll
            for (int nf = 0; nf < 8; nf++) {
                uint32_t b0 = *(const uint32_t*)&Kh[nf*8 + g][kb];
                uint32_t b1 = *(const uint32_t*)&Kh[nf*8 + g][kb + 8];
                uint32_t c0r = *(const uint32_t*)&Kl[nf*8 + g][kb];
                uint32_t c1r = *(const uint32_t*)&Kl[nf*8 + g][kb + 8];
                MMA_BF16(s[nf], ah[0], ah[1], ah[2], ah[3], b0, b1);
                MMA_BF16(s[nf], ah[0], ah[1], ah[2], ah[3], c0r, c1r);
                MMA_BF16(s[nf], al[0], al[1], al[2], al[3], b0, b1);
            }
        }

        // scale + alibi + causal
        #pragma unroll
        for (int nf = 0; nf < 8; nf++) {
            const int col = kt*64 + nf*8 + 2*t;
            const int c1 = col + 1;
            s[nf][0] = (col > row0) ? -CUDART_INF_F
                     : s[nf][0]*0.125f - slope*(float)(row0 - col);
            s[nf][1] = (c1  > row0) ? -CUDART_INF_F
                     : s[nf][1]*0.125f - slope*(float)(row0 - c1);
            s[nf][2] = (col > row1) ? -CUDART_INF_F
                     : s[nf][2]*0.125f - slope*(float)(row1 - col);
            s[nf][3] = (c1  > row1) ? -CUDART_INF_F
                     : s[nf][3]*0.125f - slope*(float)(row1 - c1);
        }

        // online softmax (rows row0, row1); quad shuffles (offsets 1,2)
        float mx0 = -CUDART_INF_F, mx1 = -CUDART_INF_F;
        #pragma unroll
        for (int nf = 0; nf < 8; nf++) {
            mx0 = fmaxf(mx0, fmaxf(s[nf][0], s[nf][1]));
            mx1 = fmaxf(mx1, fmaxf(s[nf][2], s[nf][3]));
        }
        mx0 = fmaxf(mx0, __shfl_xor_sync(0xffffffffu, mx0, 1));
        mx0 = fmaxf(mx0, __shfl_xor_sync(0xffffffffu, mx0, 2));
        mx1 = fmaxf(mx1, __shfl_xor_sync(0xffffffffu, mx1, 1));
        mx1 = fmaxf(mx1, __shfl_xor_sync(0xffffffffu, mx1, 2));

        const float mn0 = fmaxf(m[0], mx0);
        const float mn1 = fmaxf(m[1], mx1);
        const float al0 = __expf(m[0] - mn0);
        const float al1 = __expf(m[1] - mn1);
        float rs0 = 0.f, rs1 = 0.f;
        #pragma unroll
        for (int nf = 0; nf < 8; nf++) {
            s[nf][0] = __expf(s[nf][0] - mn0); rs0 += s[nf][0];
            s[nf][1] = __expf(s[nf][1] - mn0); rs0 += s[nf][1];
            s[nf][2] = __expf(s[nf][2] - mn1); rs1 += s[nf][2];
            s[nf][3] = __expf(s[nf][3] - mn1); rs1 += s[nf][3];
        }
        rs0 += __shfl_xor_sync(0xffffffffu, rs0, 1);
        rs0 += __shfl_xor_sync(0xffffffffu, rs0, 2);
        rs1 += __shfl_xor_sync(0xffffffffu, rs1, 1);
        rs1 += __shfl_xor_sync(0xffffffffu, rs1, 2);
        l[0] = l[0]*al0 + rs0; m[0] = mn0;
        l[1] = l[1]*al1 + rs1; m[1] = mn1;
        #pragma unroll
        for (int dn = 0; dn < 8; dn++) {
            o[dn][0] *= al0; o[dn][1] *= al0;
            o[dn][2] *= al1; o[dn][3] *= al1;
        }

        // O += P @ V : P fragments packed straight from registers
        #pragma unroll
        for (int ks = 0; ks < 4; ks++) {
            uint32_t ph[4], pl[4];
            split2(s[2*ks][0],   s[2*ks][1],   ph[0], pl[0]);
            split2(s[2*ks][2],   s[2*ks][3],   ph[1], pl[1]);
            split2(s[2*ks+1][0], s[2*ks+1][1], ph[2], pl[2]);
            split2(s[2*ks+1][2], s[2*ks+1][3], ph[3], pl[3]);
            const int kb = ks*16 + 2*t;
            #pragma unroll
            for (int dn = 0; dn < 8; dn++) {
                uint32_t b0 = *(const uint32_t*)&Vh[dn*8 + g][kb];
                uint32_t b1 = *(const uint32_t*)&Vh[dn*8 + g][kb + 8];
                uint32_t c0r = *(const uint32_t*)&Vl[dn*8 + g][kb];
                uint32_t c1r = *(const uint32_t*)&Vl[dn*8 + g][kb + 8];
                MMA_BF16(o[dn], ph[0], ph[1], ph[2], ph[3], b0, b1);
                MMA_BF16(o[dn], ph[0], ph[1], ph[2], ph[3], c0r, c1r);
                MMA_BF16(o[dn], pl[0], pl[1], pl[2], pl[3], b0, b1);
            }
        }
    }

    // normalize + store to [B,S,E] context buffer
    const float inv0 = 1.f / l[0];
    const float inv1 = 1.f / l[1];
    float* out0 = att + ((size_t)(b*SQ + row0))*EE + h*DD;
    float* out1 = att + ((size_t)(b*SQ + row1))*EE + h*DD;
    #pragma unroll
    for (int dn = 0; dn < 8; dn++) {
        const int d = dn*8 + 2*t;
        *(float2*)(out0 + d) = make_float2(o[dn][0]*inv0, o[dn][1]*inv0);
        *(float2*)(out1 + d) = make_float2(o[dn][2]*inv1, o[dn][3]*inv1);
    }
}

// ---------------------------------------------------------------------------
// Head-0 attention probabilities (second output). One CTA per (query row, b).
// ---------------------------------------------------------------------------
__global__ __launch_bounds__(256) void attn0_kernel(
    const float* __restrict__ qh, const float* __restrict__ kh,
    float* __restrict__ attn_out)
{
    __shared__ float qrow[64];
    __shared__ float lg[SQ];
    __shared__ float redmax[8];
    __shared__ float redsum[8];

    const int i = (SQ - 1) - blockIdx.x;    // biggest rows first
    const int b = blockIdx.y;
    const float* Q = qh + ((size_t)(b*HH)*SQ + i)*DD;
    const float* K = kh + (size_t)(b*HH)*SQ*DD;
    const int tid = threadIdx.x;

    if (tid < 64) qrow[tid] = Q[tid];
    __syncthreads();

    const float slope = 0.70710678118654752f;  // 2^-0.5 (head 1 of 16)
    float lmax = -CUDART_INF_F;
    for (int j = tid; j <= i; j += 256) {
        const float4* kp = (const float4*)(K + (size_t)j*DD);
        float dot = 0.f;
        #pragma unroll
        for (int d4 = 0; d4 < 16; d4++) {
            float4 kv = kp[d4];
            float4 qv = *(const float4*)&qrow[d4*4];
            dot += kv.x*qv.x + kv.y*qv.y + kv.z*qv.z + kv.w*qv.w;
        }
        const float v = dot*0.125f - slope*(float)(i - j);
        lg[j] = v;
        lmax = fmaxf(lmax, v);
    }
    #pragma unroll
    for (int off = 16; off; off >>= 1)
        lmax = fmaxf(lmax, __shfl_xor_sync(0xffffffffu, lmax, off));
    if ((tid & 31) == 0) redmax[tid >> 5] = lmax;
    __syncthreads();
    float gmax = redmax[0];
    #pragma unroll
    for (int w = 1; w < 8; w++) gmax = fmaxf(gmax, redmax[w]);

    float psum = 0.f;
    for (int j = tid; j <= i; j += 256) {
        const float p = __expf(lg[j] - gmax);
        lg[j] = p;
        psum += p;
    }
    #pragma unroll
    for (int off = 16; off; off >>= 1)
        psum += __shfl_xor_sync(0xffffffffu, psum, off);
    if ((tid & 31) == 0) redsum[tid >> 5] = psum;
    __syncthreads();
    float gsum = 0.f;
    #pragma unroll
    for (int w = 0; w < 8; w++) gsum += redsum[w];
    const float inv = 1.f / gsum;

    float* outp = attn_out + ((size_t)(b*SQ + i))*SQ;
    for (int j = tid; j < SQ; j += 256)
        outp[j] = (j <= i) ? lg[j]*inv : 0.f;
}

// ---------------------------------------------------------------------------
extern "C" void kernel_launch(void* const* d_in, const int* in_sizes, int n_in,
                              void* d_out, int out_size)
{
    const float* q  = (const float*)d_in[0];
    const float* k  = (const float*)d_in[1];
    const float* v  = (const float*)d_in[2];
    // d_in[3] = alibi, d_in[4] = mask  (computed analytically in-kernel)
    const float* wq = (const float*)d_in[5];
    const float* wk = (const float*)d_in[6];
    const float* wv = (const float*)d_in[7];
    const float* wd = (const float*)d_in[8];
    const float* bd = (const float*)d_in[9];

    // Device-function attribute (not a stream op; capture-safe).
    cudaFuncSetAttribute(flash_mma,
                         cudaFuncAttributeMaxDynamicSharedMemorySize, 55296);

    float *qh, *kh, *vh, *att;
    cudaGetSymbolAddress((void**)&qh,  g_qh);
    cudaGetSymbolAddress((void**)&kh,  g_kh);
    cudaGetSymbolAddress((void**)&vh,  g_vh);
    cudaGetSymbolAddress((void**)&att, g_att);

    float* out_main = (float*)d_out;                       // [B,S,E]
    float* out_attn = (float*)d_out + (size_t)MM*EE;       // [B,S,S]

    const dim3 gemm_grid(EE/128, MM/128);   // 8 x 32

    gemm_bf16x3<<<gemm_grid, 256>>>(q, wq, nullptr, qh, MM, EE, EE, 1);
    gemm_bf16x3<<<gemm_grid, 256>>>(k, wk, nullptr, kh, MM, EE, EE, 1);
    gemm_bf16x3<<<gemm_grid, 256>>>(v, wv, nullptr, vh, MM, EE, EE, 1);

    flash_mma<<<dim3(SQ/64, HH, BB), 128, 55296>>>(qh, kh, vh, att);

    attn0_kernel<<<dim3(SQ, BB), 256>>>(qh, kh, out_attn);

    gemm_bf16x3<<<gemm_grid, 256>>>(att, wd, bd, out_main, MM, EE, EE, 0);
}

// round 8
// speedup vs baseline: 2.3497x; 1.0492x over previous
#include <cuda_runtime.h>
#include <cuda_bf16.h>
#include <math_constants.h>
#include <cstdint>

// Problem constants
#define BB 2
#define SQ 2048
#define EE 1024
#define HH 16
#define DD 64
#define MM (BB*SQ)   // 4096 rows

// ---------------------------------------------------------------------------
// Scratch (device globals: allocation-free rule). All bf16 stored as ushort.
// ---------------------------------------------------------------------------
__device__ unsigned short g_sqh[MM*EE], g_sql[MM*EE];   // split q input [M][K]
__device__ unsigned short g_skh[MM*EE], g_skl[MM*EE];   // split k input
__device__ unsigned short g_svh[MM*EE], g_svl[MM*EE];   // split v input
__device__ unsigned short g_wqh[EE*EE], g_wql[EE*EE];   // split weights [N][K]
__device__ unsigned short g_wkh[EE*EE], g_wkl[EE*EE];
__device__ unsigned short g_wvh[EE*EE], g_wvl[EE*EE];
__device__ unsigned short g_wdh[EE*EE], g_wdl[EE*EE];
__device__ unsigned short g_qhh[MM*EE], g_qhl[MM*EE];   // Q heads [B,H,S,D]
__device__ unsigned short g_khh[MM*EE], g_khl[MM*EE];   // K heads [B,H,S,D]
__device__ unsigned short g_vth[MM*EE], g_vtl[MM*EE];   // V heads transposed [B,H,D,S]
__device__ float          g_q0[BB*SQ*DD], g_k0[BB*SQ*DD]; // fp32 head-0 (attn0)
__device__ unsigned short g_atth[MM*EE], g_attl[MM*EE]; // context [B,S,E]

#define MMA_BF16(cc, A0, A1, A2, A3, B0, B1)                                  \
    asm volatile("mma.sync.aligned.m16n8k16.row.col.f32.bf16.bf16.f32 "       \
                 "{%0,%1,%2,%3}, {%4,%5,%6,%7}, {%8,%9}, {%0,%1,%2,%3};"      \
                 : "+f"(cc[0]), "+f"(cc[1]), "+f"(cc[2]), "+f"(cc[3])         \
                 : "r"(A0), "r"(A1), "r"(A2), "r"(A3), "r"(B0), "r"(B1))

__device__ __forceinline__ uint32_t pack_bf16(__nv_bfloat16 lo16, __nv_bfloat16 hi16) {
    return (uint32_t)__bfloat16_as_ushort(lo16) |
           ((uint32_t)__bfloat16_as_ushort(hi16) << 16);
}
__device__ __forceinline__ void split2(float a, float b, uint32_t& hi, uint32_t& lo) {
    __nv_bfloat16 ha = __float2bfloat16(a), hb = __float2bfloat16(b);
    __nv_bfloat16 la = __float2bfloat16(a - __bfloat162float(ha));
    __nv_bfloat16 lb = __float2bfloat16(b - __bfloat162float(hb));
    hi = pack_bf16(ha, hb);
    lo = pack_bf16(la, lb);
}
__device__ __forceinline__ void split1(float a, unsigned short& h, unsigned short& l) {
    __nv_bfloat16 ha = __float2bfloat16(a);
    __nv_bfloat16 la = __float2bfloat16(a - __bfloat162float(ha));
    h = __bfloat16_as_ushort(ha);
    l = __bfloat16_as_ushort(la);
}

// ---------------------------------------------------------------------------
// Pre-pass: split fp32 array into bf16 hi/lo.
// ---------------------------------------------------------------------------
__global__ __launch_bounds__(256) void split_kernel(
    const float* __restrict__ src, unsigned short* __restrict__ hi,
    unsigned short* __restrict__ lo, int n)
{
    const int i = (blockIdx.x * 256 + threadIdx.x) * 4;
    if (i >= n) return;
    float4 v = *(const float4*)(src + i);
    uint32_t h01, l01, h23, l23;
    split2(v.x, v.y, h01, l01);
    split2(v.z, v.w, h23, l23);
    *(uint32_t*)(hi + i)     = h01; *(uint32_t*)(hi + i + 2) = h23;
    *(uint32_t*)(lo + i)     = l01; *(uint32_t*)(lo + i + 2) = l23;
}

// ---------------------------------------------------------------------------
// Tensor-core GEMM on pre-split bf16: C = A @ W^T (3-mma compensated).
// 128x128x16 tiles, 8 warps, double-buffered.
// mode 0: fp32 out [M][N] (+bias). mode 1: bf16 hi/lo head layout + fp32
// head-0 aux. mode 2: bf16 hi/lo transposed head layout [B,H,D,S].
// ---------------------------------------------------------------------------
__global__ __launch_bounds__(256, 2) void gemm_pre(
    const unsigned short* __restrict__ Ahg, const unsigned short* __restrict__ Alg,
    const unsigned short* __restrict__ Whg, const unsigned short* __restrict__ Wlg,
    const float* __restrict__ bias, float* __restrict__ Cf,
    unsigned short* __restrict__ Chi, unsigned short* __restrict__ Clo,
    float* __restrict__ Caux,
    int M, int N, int K, int mode)
{
    __shared__ unsigned short Ah[2][128][24];
    __shared__ unsigned short Al[2][128][24];
    __shared__ unsigned short Bh[2][128][24];
    __shared__ unsigned short Bl[2][128][24];

    const int m0 = blockIdx.y * 128;
    const int n0 = blockIdx.x * 128;
    const int tid  = threadIdx.x;
    const int wid  = tid >> 5, lane = tid & 31;
    const int g    = lane >> 2, tig = lane & 3;
    const int wr   = (wid >> 2) * 64;
    const int wc   = (wid & 3) * 32;

    // Fill: thread copies one uint4 (8 halves) per array per stage.
    const int fm = tid >> 1;              // 0..127
    const int fs = (tid & 1) * 8;         // 0 or 8
    const size_t aoff = (size_t)(m0 + fm) * K + fs;
    const size_t woff = (size_t)(n0 + fm) * K + fs;

    float c[4][4][4];
    #pragma unroll
    for (int mf = 0; mf < 4; mf++)
        #pragma unroll
        for (int nf = 0; nf < 4; nf++)
            #pragma unroll
            for (int r = 0; r < 4; r++) c[mf][nf][r] = 0.f;

    *(uint4*)&Ah[0][fm][fs] = *(const uint4*)(Ahg + aoff);
    *(uint4*)&Al[0][fm][fs] = *(const uint4*)(Alg + aoff);
    *(uint4*)&Bh[0][fm][fs] = *(const uint4*)(Whg + woff);
    *(uint4*)&Bl[0][fm][fs] = *(const uint4*)(Wlg + woff);
    __syncthreads();

    const int NT = K / 16;
    int cur = 0;
    for (int kt = 0; kt < NT; kt++) {
        uint4 ra, rl, rwh, rwl;
        const bool more = (kt + 1) < NT;
        if (more) {
            const int ko = (kt + 1) * 16;
            ra  = *(const uint4*)(Ahg + aoff + ko);
            rl  = *(const uint4*)(Alg + aoff + ko);
            rwh = *(const uint4*)(Whg + woff + ko);
            rwl = *(const uint4*)(Wlg + woff + ko);
        }

        uint32_t a[4][4], bhr[4][2], blr[4][2];
        #pragma unroll
        for (int mf = 0; mf < 4; mf++) {
            const int rb = wr + mf * 16;
            a[mf][0] = *(const uint32_t*)&Ah[cur][rb + g    ][2 * tig];
            a[mf][1] = *(const uint32_t*)&Ah[cur][rb + 8 + g][2 * tig];
            a[mf][2] = *(const uint32_t*)&Ah[cur][rb + g    ][2 * tig + 8];
            a[mf][3] = *(const uint32_t*)&Ah[cur][rb + 8 + g][2 * tig + 8];
        }
        #pragma unroll
        for (int nf = 0; nf < 4; nf++) {
            const int cb = wc + nf * 8;
            bhr[nf][0] = *(const uint32_t*)&Bh[cur][cb + g][2 * tig];
            bhr[nf][1] = *(const uint32_t*)&Bh[cur][cb + g][2 * tig + 8];
            blr[nf][0] = *(const uint32_t*)&Bl[cur][cb + g][2 * tig];
            blr[nf][1] = *(const uint32_t*)&Bl[cur][cb + g][2 * tig + 8];
        }
        #pragma unroll
        for (int mf = 0; mf < 4; mf++)
            #pragma unroll
            for (int nf = 0; nf < 4; nf++) {
                MMA_BF16(c[mf][nf], a[mf][0], a[mf][1], a[mf][2], a[mf][3],
                         bhr[nf][0], bhr[nf][1]);
                MMA_BF16(c[mf][nf], a[mf][0], a[mf][1], a[mf][2], a[mf][3],
                         blr[nf][0], blr[nf][1]);
            }
        #pragma unroll
        for (int mf = 0; mf < 4; mf++) {
            const int rb = wr + mf * 16;
            a[mf][0] = *(const uint32_t*)&Al[cur][rb + g    ][2 * tig];
            a[mf][1] = *(const uint32_t*)&Al[cur][rb + 8 + g][2 * tig];
            a[mf][2] = *(const uint32_t*)&Al[cur][rb + g    ][2 * tig + 8];
            a[mf][3] = *(const uint32_t*)&Al[cur][rb + 8 + g][2 * tig + 8];
        }
        #pragma unroll
        for (int mf = 0; mf < 4; mf++)
            #pragma unroll
            for (int nf = 0; nf < 4; nf++)
                MMA_BF16(c[mf][nf], a[mf][0], a[mf][1], a[mf][2], a[mf][3],
                         bhr[nf][0], bhr[nf][1]);

        if (more) {
            const int nxt = cur ^ 1;
            *(uint4*)&Ah[nxt][fm][fs] = ra;
            *(uint4*)&Al[nxt][fm][fs] = rl;
            *(uint4*)&Bh[nxt][fm][fs] = rwh;
            *(uint4*)&Bl[nxt][fm][fs] = rwl;
        }
        __syncthreads();
        cur ^= 1;
    }

    // Epilogue
    #pragma unroll
    for (int mf = 0; mf < 4; mf++) {
        #pragma unroll
        for (int nf = 0; nf < 4; nf++) {
            const int r  = m0 + wr + mf * 16 + g;
            const int cc = n0 + wc + nf * 8 + 2 * tig;
            float v0 = c[mf][nf][0], v1 = c[mf][nf][1];
            float v2 = c[mf][nf][2], v3 = c[mf][nf][3];
            if (mode == 0) {
                const float b0 = bias[cc], b1 = bias[cc + 1];
                v0 += b0; v1 += b1; v2 += b0; v3 += b1;
                *(float2*)(Cf + (size_t)r * N + cc)       = make_float2(v0, v1);
                *(float2*)(Cf + (size_t)(r + 8) * N + cc) = make_float2(v2, v3);
            } else {
                const int b = r >> 11, s = r & 2047;
                const int h = cc >> 6, d = cc & 63;
                if (mode == 1) {
                    uint32_t h01, l01, h23, l23;
                    split2(v0, v1, h01, l01);
                    split2(v2, v3, h23, l23);
                    const size_t i0 = ((size_t)(b * HH + h) * SQ + s) * DD + d;
                    const size_t i1 = i0 + 8 * DD;   // s+8, same b/h
                    *(uint32_t*)&Chi[i0] = h01; *(uint32_t*)&Clo[i0] = l01;
                    *(uint32_t*)&Chi[i1] = h23; *(uint32_t*)&Clo[i1] = l23;
                    if (h == 0) {
                        const size_t a0 = ((size_t)b * SQ + s) * DD + d;
                        *(float2*)(Caux + a0)           = make_float2(v0, v1);
                        *(float2*)(Caux + a0 + 8 * DD)  = make_float2(v2, v3);
                    }
                } else {  // mode 2: transposed [B,H,D,S]
                    const size_t base = ((size_t)(b * HH + h) * DD + d) * SQ;
                    unsigned short hh, ll;
                    split1(v0, hh, ll); Chi[base + s]          = hh; Clo[base + s]          = ll;
                    split1(v1, hh, ll); Chi[base + SQ + s]     = hh; Clo[base + SQ + s]     = ll;
                    split1(v2, hh, ll); Chi[base + s + 8]      = hh; Clo[base + s + 8]      = ll;
                    split1(v3, hh, ll); Chi[base + SQ + s + 8] = hh; Clo[base + SQ + s + 8] = ll;
                }
            }
        }
    }
}

// ---------------------------------------------------------------------------
// Tensor-core flash attention (causal + ALiBi), all operands pre-split bf16.
// CTA = 64 q-rows, one (b,h). 128 threads. Emits context as bf16 hi/lo.
// Dynamic smem 55296B: Qh/Ql [q][d], Kh/Kl [kcol][d], Vh/Vl [d][kcol],
// each 64x72 halves (72-half stride -> conflict-free fragment LDS).
// ---------------------------------------------------------------------------
__global__ __launch_bounds__(128) void flash_mma(
    const unsigned short* __restrict__ qhh, const unsigned short* __restrict__ qhl,
    const unsigned short* __restrict__ khh, const unsigned short* __restrict__ khl,
    const unsigned short* __restrict__ vth, const unsigned short* __restrict__ vtl,
    unsigned short* __restrict__ atth, unsigned short* __restrict__ attl)
{
    extern __shared__ unsigned short fsm[];
    typedef unsigned short (*arr72)[72];
    arr72 Qh = (arr72)(fsm);
    arr72 Ql = (arr72)(fsm + 4608);
    arr72 Kh = (arr72)(fsm + 9216);
    arr72 Kl = (arr72)(fsm + 13824);
    arr72 Vh = (arr72)(fsm + 18432);
    arr72 Vl = (arr72)(fsm + 23040);

    const int qt = (SQ/64 - 1) - blockIdx.x;   // biggest tiles first
    const int h  = blockIdx.y;
    const int b  = blockIdx.z;
    const int bh = b*HH + h;
    const unsigned short* Qhg = qhh + (size_t)bh*SQ*DD + (size_t)qt*64*DD;
    const unsigned short* Qlg = qhl + (size_t)bh*SQ*DD + (size_t)qt*64*DD;
    const unsigned short* Khg = khh + (size_t)bh*SQ*DD;
    const unsigned short* Klg = khl + (size_t)bh*SQ*DD;
    const unsigned short* Vhg = vth + (size_t)bh*DD*SQ;
    const unsigned short* Vlg = vtl + (size_t)bh*DD*SQ;

    const int tid  = threadIdx.x;
    const int wid  = tid >> 5, lane = tid & 31;
    const int g    = lane >> 2, t = lane & 3;
    const int wr   = wid * 16;

    // Load Q tile: pure uint4 copies (64x64 halves per array)
    #pragma unroll
    for (int i = 0; i < 4; i++) {
        const int idx = tid + 128*i;           // 0..511
        const int row = idx >> 3, c8 = (idx & 7)*8;
        *(uint4*)&Qh[row][c8] = *(const uint4*)(Qhg + row*DD + c8);
        *(uint4*)&Ql[row][c8] = *(const uint4*)(Qlg + row*DD + c8);
    }

    float o[8][4];
    float m[2], l[2];
    #pragma unroll
    for (int dn = 0; dn < 8; dn++)
        #pragma unroll
        for (int r = 0; r < 4; r++) o[dn][r] = 0.f;
    m[0] = m[1] = -CUDART_INF_F;
    l[0] = l[1] = 0.f;

    const float slope = exp2f(-0.5f*(float)(h+1));
    const int row0 = qt*64 + wr + g;
    const int row1 = row0 + 8;

    for (int kt = 0; kt <= qt; kt++) {
        __syncthreads();   // prior PV reads complete before overwrite
        #pragma unroll
        for (int i = 0; i < 4; i++) {
            const int idx = tid + 128*i;
            const int row = idx >> 3, c8 = (idx & 7)*8;
            *(uint4*)&Kh[row][c8] = *(const uint4*)(Khg + (size_t)(kt*64+row)*DD + c8);
            *(uint4*)&Kl[row][c8] = *(const uint4*)(Klg + (size_t)(kt*64+row)*DD + c8);
            *(uint4*)&Vh[row][c8] = *(const uint4*)(Vhg + (size_t)row*SQ + kt*64 + c8);
            *(uint4*)&Vl[row][c8] = *(const uint4*)(Vlg + (size_t)row*SQ + kt*64 + c8);
        }
        __syncthreads();

        // S = Q @ K^T  (3-mma split)
        float s[8][4];
        #pragma unroll
        for (int nf = 0; nf < 8; nf++)
            #pragma unroll
            for (int r = 0; r < 4; r++) s[nf][r] = 0.f;

        #pragma unroll
        for (int ks = 0; ks < 4; ks++) {
            const int kb = ks*16 + 2*t;
            uint32_t ah[4], al[4];
            ah[0] = *(const uint32_t*)&Qh[wr + g    ][kb];
            ah[1] = *(const uint32_t*)&Qh[wr + 8 + g][kb];
            ah[2] = *(const uint32_t*)&Qh[wr + g    ][kb + 8];
            ah[3] = *(const uint32_t*)&Qh[wr + 8 + g][kb + 8];
            al[0] = *(const uint32_t*)&Ql[wr + g    ][kb];
            al[1] = *(const uint32_t*)&Ql[wr + 8 + g][kb];
            al[2] = *(const uint32_t*)&Ql[wr + g    ][kb + 8];
            al[3] = *(const uint32_t*)&Ql[wr + 8 + g][kb + 8];
            #pragma unroll
            for (int nf = 0; nf < 8; nf++) {
                uint32_t b0 = *(const uint32_t*)&Kh[nf*8 + g][kb];
                uint32_t b1 = *(const uint32_t*)&Kh[nf*8 + g][kb + 8];
                uint32_t c0r = *(const uint32_t*)&Kl[nf*8 + g][kb];
                uint32_t c1r = *(const uint32_t*)&Kl[nf*8 + g][kb + 8];
                MMA_BF16(s[nf], ah[0], ah[1], ah[2], ah[3], b0, b1);
                MMA_BF16(s[nf], ah[0], ah[1], ah[2], ah[3], c0r, c1r);
                MMA_BF16(s[nf], al[0], al[1], al[2], al[3], b0, b1);
            }
        }

        // scale + alibi + causal
        #pragma unroll
        for (int nf = 0; nf < 8; nf++) {
            const int col = kt*64 + nf*8 + 2*t;
            const int c1 = col + 1;
            s[nf][0] = (col > row0) ? -CUDART_INF_F
                     : s[nf][0]*0.125f - slope*(float)(row0 - col);
            s[nf][1] = (c1  > row0) ? -CUDART_INF_F
                     : s[nf][1]*0.125f - slope*(float)(row0 - c1);
            s[nf][2] = (col > row1) ? -CUDART_INF_F
                     : s[nf][2]*0.125f - slope*(float)(row1 - col);
            s[nf][3] = (c1  > row1) ? -CUDART_INF_F
                     : s[nf][3]*0.125f - slope*(float)(row1 - c1);
        }

        // online softmax (rows row0, row1); quad shuffles (offsets 1,2)
        float mx0 = -CUDART_INF_F, mx1 = -CUDART_INF_F;
        #pragma unroll
        for (int nf = 0; nf < 8; nf++) {
            mx0 = fmaxf(mx0, fmaxf(s[nf][0], s[nf][1]));
            mx1 = fmaxf(mx1, fmaxf(s[nf][2], s[nf][3]));
        }
        mx0 = fmaxf(mx0, __shfl_xor_sync(0xffffffffu, mx0, 1));
        mx0 = fmaxf(mx0, __shfl_xor_sync(0xffffffffu, mx0, 2));
        mx1 = fmaxf(mx1, __shfl_xor_sync(0xffffffffu, mx1, 1));
        mx1 = fmaxf(mx1, __shfl_xor_sync(0xffffffffu, mx1, 2));

        const float mn0 = fmaxf(m[0], mx0);
        const float mn1 = fmaxf(m[1], mx1);
        const float al0 = __expf(m[0] - mn0);
        const float al1 = __expf(m[1] - mn1);
        float rs0 = 0.f, rs1 = 0.f;
        #pragma unroll
        for (int nf = 0; nf < 8; nf++) {
            s[nf][0] = __expf(s[nf][0] - mn0); rs0 += s[nf][0];
            s[nf][1] = __expf(s[nf][1] - mn0); rs0 += s[nf][1];
            s[nf][2] = __expf(s[nf][2] - mn1); rs1 += s[nf][2];
            s[nf][3] = __expf(s[nf][3] - mn1); rs1 += s[nf][3];
        }
        rs0 += __shfl_xor_sync(0xffffffffu, rs0, 1);
        rs0 += __shfl_xor_sync(0xffffffffu, rs0, 2);
        rs1 += __shfl_xor_sync(0xffffffffu, rs1, 1);
        rs1 += __shfl_xor_sync(0xffffffffu, rs1, 2);
        l[0] = l[0]*al0 + rs0; m[0] = mn0;
        l[1] = l[1]*al1 + rs1; m[1] = mn1;
        #pragma unroll
        for (int dn = 0; dn < 8; dn++) {
            o[dn][0] *= al0; o[dn][1] *= al0;
            o[dn][2] *= al1; o[dn][3] *= al1;
        }

        // O += P @ V : P fragments packed straight from registers
        #pragma unroll
        for (int ks = 0; ks < 4; ks++) {
            uint32_t ph[4], pl[4];
            split2(s[2*ks][0],   s[2*ks][1],   ph[0], pl[0]);
            split2(s[2*ks][2],   s[2*ks][3],   ph[1], pl[1]);
            split2(s[2*ks+1][0], s[2*ks+1][1], ph[2], pl[2]);
            split2(s[2*ks+1][2], s[2*ks+1][3], ph[3], pl[3]);
            const int kb = ks*16 + 2*t;
            #pragma unroll
            for (int dn = 0; dn < 8; dn++) {
                uint32_t b0 = *(const uint32_t*)&Vh[dn*8 + g][kb];
                uint32_t b1 = *(const uint32_t*)&Vh[dn*8 + g][kb + 8];
                uint32_t c0r = *(const uint32_t*)&Vl[dn*8 + g][kb];
                uint32_t c1r = *(const uint32_t*)&Vl[dn*8 + g][kb + 8];
                MMA_BF16(o[dn], ph[0], ph[1], ph[2], ph[3], b0, b1);
                MMA_BF16(o[dn], ph[0], ph[1], ph[2], ph[3], c0r, c1r);
                MMA_BF16(o[dn], pl[0], pl[1], pl[2], pl[3], b0, b1);
            }
        }
    }

    // normalize + store context as bf16 hi/lo [B,S,E]
    const float inv0 = 1.f / l[0];
    const float inv1 = 1.f / l[1];
    const size_t o0 = ((size_t)(b*SQ + row0))*EE + h*DD;
    const size_t o1 = ((size_t)(b*SQ + row1))*EE + h*DD;
    #pragma unroll
    for (int dn = 0; dn < 8; dn++) {
        const int d = dn*8 + 2*t;
        uint32_t hh, ll;
        split2(o[dn][0]*inv0, o[dn][1]*inv0, hh, ll);
        *(uint32_t*)&atth[o0 + d] = hh; *(uint32_t*)&attl[o0 + d] = ll;
        split2(o[dn][2]*inv1, o[dn][3]*inv1, hh, ll);
        *(uint32_t*)&atth[o1 + d] = hh; *(uint32_t*)&attl[o1 + d] = ll;
    }
}

// ---------------------------------------------------------------------------
// Head-0 attention probabilities (second output). One CTA per (query row, b).
// Reads fp32 head-0 aux buffers [B,S,D].
// ---------------------------------------------------------------------------
__global__ __launch_bounds__(256) void attn0_kernel(
    const float* __restrict__ q0, const float* __restrict__ k0,
    float* __restrict__ attn_out)
{
    __shared__ float qrow[64];
    __shared__ float lg[SQ];
    __shared__ float redmax[8];
    __shared__ float redsum[8];

    const int i = (SQ - 1) - blockIdx.x;    // biggest rows first
    const int b = blockIdx.y;
    const float* Q = q0 + ((size_t)(b*SQ) + i)*DD;
    const float* K = k0 + (size_t)b*SQ*DD;
    const int tid = threadIdx.x;

    if (tid < 64) qrow[tid] = Q[tid];
    __syncthreads();

    const float slope = 0.70710678118654752f;  // 2^-0.5 (head 1 of 16)
    float lmax = -CUDART_INF_F;
    for (int j = tid; j <= i; j += 256) {
        const float4* kp = (const float4*)(K + (size_t)j*DD);
        float dot = 0.f;
        #pragma unroll
        for (int d4 = 0; d4 < 16; d4++) {
            float4 kv = kp[d4];
            float4 qv = *(const float4*)&qrow[d4*4];
            dot += kv.x*qv.x + kv.y*qv.y + kv.z*qv.z + kv.w*qv.w;
        }
        const float v = dot*0.125f - slope*(float)(i - j);
        lg[j] = v;
        lmax = fmaxf(lmax, v);
    }
    #pragma unroll
    for (int off = 16; off; off >>= 1)
        lmax = fmaxf(lmax, __shfl_xor_sync(0xffffffffu, lmax, off));
    if ((tid & 31) == 0) redmax[tid >> 5] = lmax;
    __syncthreads();
    float gmax = redmax[0];
    #pragma unroll
    for (int w = 1; w < 8; w++) gmax = fmaxf(gmax, redmax[w]);

    float psum = 0.f;
    for (int j = tid; j <= i; j += 256) {
        const float p = __expf(lg[j] - gmax);
        lg[j] = p;
        psum += p;
    }
    #pragma unroll
    for (int off = 16; off; off >>= 1)
        psum += __shfl_xor_sync(0xffffffffu, psum, off);
    if ((tid & 31) == 0) redsum[tid >> 5] = psum;
    __syncthreads();
    float gsum = 0.f;
    #pragma unroll
    for (int w = 0; w < 8; w++) gsum += redsum[w];
    const float inv = 1.f / gsum;

    float* outp = attn_out + ((size_t)(b*SQ + i))*SQ;
    for (int j = tid; j < SQ; j += 256)
        outp[j] = (j <= i) ? lg[j]*inv : 0.f;
}

// ---------------------------------------------------------------------------
extern "C" void kernel_launch(void* const* d_in, const int* in_sizes, int n_in,
                              void* d_out, int out_size)
{
    const float* q  = (const float*)d_in[0];
    const float* k  = (const float*)d_in[1];
    const float* v  = (const float*)d_in[2];
    // d_in[3] = alibi, d_in[4] = mask  (computed analytically in-kernel)
    const float* wq = (const float*)d_in[5];
    const float* wk = (const float*)d_in[6];
    const float* wv = (const float*)d_in[7];
    const float* wd = (const float*)d_in[8];
    const float* bd = (const float*)d_in[9];

    cudaFuncSetAttribute(flash_mma,
                         cudaFuncAttributeMaxDynamicSharedMemorySize, 55296);

    unsigned short *sqh, *sql, *skh, *skl, *svh, *svl;
    unsigned short *wqh_, *wql_, *wkh_, *wkl_, *wvh_, *wvl_, *wdh_, *wdl_;
    unsigned short *qhh, *qhl, *khh, *khl, *vth, *vtl, *atth, *attl;
    float *q0, *k0;
    cudaGetSymbolAddress((void**)&sqh,  g_sqh);  cudaGetSymbolAddress((void**)&sql,  g_sql);
    cudaGetSymbolAddress((void**)&skh,  g_skh);  cudaGetSymbolAddress((void**)&skl,  g_skl);
    cudaGetSymbolAddress((void**)&svh,  g_svh);  cudaGetSymbolAddress((void**)&svl,  g_svl);
    cudaGetSymbolAddress((void**)&wqh_, g_wqh);  cudaGetSymbolAddress((void**)&wql_, g_wql);
    cudaGetSymbolAddress((void**)&wkh_, g_wkh);  cudaGetSymbolAddress((void**)&wkl_, g_wkl);
    cudaGetSymbolAddress((void**)&wvh_, g_wvh);  cudaGetSymbolAddress((void**)&wvl_, g_wvl);
    cudaGetSymbolAddress((void**)&wdh_, g_wdh);  cudaGetSymbolAddress((void**)&wdl_, g_wdl);
    cudaGetSymbolAddress((void**)&qhh,  g_qhh);  cudaGetSymbolAddress((void**)&qhl,  g_qhl);
    cudaGetSymbolAddress((void**)&khh,  g_khh);  cudaGetSymbolAddress((void**)&khl,  g_khl);
    cudaGetSymbolAddress((void**)&vth,  g_vth);  cudaGetSymbolAddress((void**)&vtl,  g_vtl);
    cudaGetSymbolAddress((void**)&atth, g_atth); cudaGetSymbolAddress((void**)&attl, g_attl);
    cudaGetSymbolAddress((void**)&q0,   g_q0);   cudaGetSymbolAddress((void**)&k0,   g_k0);

    float* out_main = (float*)d_out;                       // [B,S,E]
    float* out_attn = (float*)d_out + (size_t)MM*EE;       // [B,S,S]

    // 1. Pre-split inputs + weights to bf16 hi/lo
    const int NIN = MM*EE, NW = EE*EE;
    split_kernel<<<NIN/1024, 256>>>(q,  sqh, sql, NIN);
    split_kernel<<<NIN/1024, 256>>>(k,  skh, skl, NIN);
    split_kernel<<<NIN/1024, 256>>>(v,  svh, svl, NIN);
    split_kernel<<<NW/1024, 256>>>(wq, wqh_, wql_, NW);
    split_kernel<<<NW/1024, 256>>>(wk, wkh_, wkl_, NW);
    split_kernel<<<NW/1024, 256>>>(wv, wvh_, wvl_, NW);
    split_kernel<<<NW/1024, 256>>>(wd, wdh_, wdl_, NW);

    const dim3 gemm_grid(EE/128, MM/128);   // 8 x 32

    // 2. Projections
    gemm_pre<<<gemm_grid, 256>>>(sqh, sql, wqh_, wql_, nullptr, nullptr,
                                 qhh, qhl, q0, MM, EE, EE, 1);
    gemm_pre<<<gemm_grid, 256>>>(skh, skl, wkh_, wkl_, nullptr, nullptr,
                                 khh, khl, k0, MM, EE, EE, 1);
    gemm_pre<<<gemm_grid, 256>>>(svh, svl, wvh_, wvl_, nullptr, nullptr,
                                 vth, vtl, nullptr, MM, EE, EE, 2);

    // 3. Flash attention -> bf16 context
    flash_mma<<<dim3(SQ/64, HH, BB), 128, 55296>>>(qhh, qhl, khh, khl,
                                                   vth, vtl, atth, attl);

    // 4. Head-0 probabilities
    attn0_kernel<<<dim3(SQ, BB), 256>>>(q0, k0, out_attn);

    // 5. Output projection
    gemm_pre<<<gemm_grid, 256>>>(atth, attl, wdh_, wdl_, bd, out_main,
                                 nullptr, nullptr, nullptr, MM, EE, EE, 0);
}

// round 10
// speedup vs baseline: 2.5689x; 1.0933x over previous
#include <cuda_runtime.h>
#include <cuda_bf16.h>
#include <math_constants.h>
#include <cstdint>

// Problem constants
#define BB 2
#define SQ 2048
#define EE 1024
#define HH 16
#define DD 64
#define MM (BB*SQ)   // 4096 rows

// ---------------------------------------------------------------------------
// Scratch (device globals: allocation-free rule). All bf16 stored as ushort.
// ---------------------------------------------------------------------------
__device__ unsigned short g_sqh[MM*EE], g_sql[MM*EE];   // split q input [M][K]
__device__ unsigned short g_skh[MM*EE], g_skl[MM*EE];   // split k input
__device__ unsigned short g_svh[MM*EE], g_svl[MM*EE];   // split v input
__device__ unsigned short g_wqh[EE*EE], g_wql[EE*EE];   // split weights [N][K]
__device__ unsigned short g_wkh[EE*EE], g_wkl[EE*EE];
__device__ unsigned short g_wvh[EE*EE], g_wvl[EE*EE];
__device__ unsigned short g_wdh[EE*EE], g_wdl[EE*EE];
__device__ unsigned short g_qhh[MM*EE], g_qhl[MM*EE];   // Q heads [B,H,S,D]
__device__ unsigned short g_khh[MM*EE], g_khl[MM*EE];   // K heads [B,H,S,D]
__device__ unsigned short g_vth[MM*EE], g_vtl[MM*EE];   // V heads transposed [B,H,D,S]
__device__ float          g_q0[BB*SQ*DD], g_k0[BB*SQ*DD]; // fp32 head-0 (attn0)
__device__ unsigned short g_atth[MM*EE], g_attl[MM*EE]; // context [B,S,E]

#define MMA_BF16(cc, A0, A1, A2, A3, B0, B1)                                  \
    asm volatile("mma.sync.aligned.m16n8k16.row.col.f32.bf16.bf16.f32 "       \
                 "{%0,%1,%2,%3}, {%4,%5,%6,%7}, {%8,%9}, {%0,%1,%2,%3};"      \
                 : "+f"(cc[0]), "+f"(cc[1]), "+f"(cc[2]), "+f"(cc[3])         \
                 : "r"(A0), "r"(A1), "r"(A2), "r"(A3), "r"(B0), "r"(B1))

__device__ __forceinline__ void ldsm_x4(uint32_t& r0, uint32_t& r1,
                                        uint32_t& r2, uint32_t& r3,
                                        const void* p) {
    uint32_t addr = (uint32_t)__cvta_generic_to_shared(p);
    asm volatile("ldmatrix.sync.aligned.m8n8.x4.shared.b16 {%0,%1,%2,%3}, [%4];"
                 : "=r"(r0), "=r"(r1), "=r"(r2), "=r"(r3) : "r"(addr));
}

__device__ __forceinline__ uint32_t pack_bf16(__nv_bfloat16 lo16, __nv_bfloat16 hi16) {
    return (uint32_t)__bfloat16_as_ushort(lo16) |
           ((uint32_t)__bfloat16_as_ushort(hi16) << 16);
}
__device__ __forceinline__ void split2(float a, float b, uint32_t& hi, uint32_t& lo) {
    __nv_bfloat16 ha = __float2bfloat16(a), hb = __float2bfloat16(b);
    __nv_bfloat16 la = __float2bfloat16(a - __bfloat162float(ha));
    __nv_bfloat16 lb = __float2bfloat16(b - __bfloat162float(hb));
    hi = pack_bf16(ha, hb);
    lo = pack_bf16(la, lb);
}
__device__ __forceinline__ void split1(float a, unsigned short& h, unsigned short& l) {
    __nv_bfloat16 ha = __float2bfloat16(a);
    __nv_bfloat16 la = __float2bfloat16(a - __bfloat162float(ha));
    h = __bfloat16_as_ushort(ha);
    l = __bfloat16_as_ushort(la);
}

// ---------------------------------------------------------------------------
// Pre-pass: split fp32 array into bf16 hi/lo.
// ---------------------------------------------------------------------------
__global__ __launch_bounds__(256) void split_kernel(
    const float* __restrict__ src, unsigned short* __restrict__ hi,
    unsigned short* __restrict__ lo, int n)
{
    const int i = (blockIdx.x * 256 + threadIdx.x) * 4;
    if (i >= n) return;
    float4 v = *(const float4*)(src + i);
    uint32_t h01, l01, h23, l23;
    split2(v.x, v.y, h01, l01);
    split2(v.z, v.w, h23, l23);
    *(uint32_t*)(hi + i)     = h01; *(uint32_t*)(hi + i + 2) = h23;
    *(uint32_t*)(lo + i)     = l01; *(uint32_t*)(lo + i + 2) = l23;
}

// ---------------------------------------------------------------------------
// Tensor-core GEMM on pre-split bf16: C = A @ W^T (3-mma compensated).
// 128x128x16 tiles, 8 warps, double-buffered, ldmatrix fragment loads.
// mode 0: fp32 out (+bias). mode 1: bf16 head layout + fp32 head-0 aux.
// mode 2: bf16 transposed head layout [B,H,D,S].
// ---------------------------------------------------------------------------
__global__ __launch_bounds__(256, 2) void gemm_pre(
    const unsigned short* __restrict__ Ahg, const unsigned short* __restrict__ Alg,
    const unsigned short* __restrict__ Whg, const unsigned short* __restrict__ Wlg,
    const float* __restrict__ bias, float* __restrict__ Cf,
    unsigned short* __restrict__ Chi, unsigned short* __restrict__ Clo,
    float* __restrict__ Caux,
    int M, int N, int K, int mode)
{
    __shared__ unsigned short Ah[2][128][24];
    __shared__ unsigned short Al[2][128][24];
    __shared__ unsigned short Bh[2][128][24];
    __shared__ unsigned short Bl[2][128][24];

    const int m0 = blockIdx.y * 128;
    const int n0 = blockIdx.x * 128;
    const int tid  = threadIdx.x;
    const int wid  = tid >> 5, lane = tid & 31;
    const int g    = lane >> 2, tig = lane & 3;
    const int wr   = (wid >> 2) * 64;
    const int wc   = (wid & 3) * 32;

    // ldmatrix lane addressing
    const int arow = (lane & 15);
    const int acol = (lane & 16) ? 8 : 0;
    const int brow = (lane & 7) + ((lane & 16) ? 8 : 0);
    const int bcol = (lane & 8) ? 8 : 0;

    // Fill: thread copies one uint4 (8 halves) per array per stage.
    const int fm = tid >> 1;              // 0..127
    const int fs = (tid & 1) * 8;         // 0 or 8
    const size_t aoff = (size_t)(m0 + fm) * K + fs;
    const size_t woff = (size_t)(n0 + fm) * K + fs;

    float c[4][4][4];
    #pragma unroll
    for (int mf = 0; mf < 4; mf++)
        #pragma unroll
        for (int nf = 0; nf < 4; nf++)
            #pragma unroll
            for (int r = 0; r < 4; r++) c[mf][nf][r] = 0.f;

    *(uint4*)&Ah[0][fm][fs] = *(const uint4*)(Ahg + aoff);
    *(uint4*)&Al[0][fm][fs] = *(const uint4*)(Alg + aoff);
    *(uint4*)&Bh[0][fm][fs] = *(const uint4*)(Whg + woff);
    *(uint4*)&Bl[0][fm][fs] = *(const uint4*)(Wlg + woff);
    __syncthreads();

    const int NT = K / 16;
    int cur = 0;
    for (int kt = 0; kt < NT; kt++) {
        uint4 ra, rl, rwh, rwl;
        const bool more = (kt + 1) < NT;
        if (more) {
            const int ko = (kt + 1) * 16;
            ra  = *(const uint4*)(Ahg + aoff + ko);
            rl  = *(const uint4*)(Alg + aoff + ko);
            rwh = *(const uint4*)(Whg + woff + ko);
            rwl = *(const uint4*)(Wlg + woff + ko);
        }

        uint32_t a[4][4], bhr[4][2], blr[4][2];
        #pragma unroll
        for (int mf = 0; mf < 4; mf++)
            ldsm_x4(a[mf][0], a[mf][1], a[mf][2], a[mf][3],
                    &Ah[cur][wr + mf*16 + arow][acol]);
        #pragma unroll
        for (int np = 0; np < 2; np++) {
            ldsm_x4(bhr[2*np][0], bhr[2*np][1], bhr[2*np+1][0], bhr[2*np+1][1],
                    &Bh[cur][wc + np*16 + brow][bcol]);
            ldsm_x4(blr[2*np][0], blr[2*np][1], blr[2*np+1][0], blr[2*np+1][1],
                    &Bl[cur][wc + np*16 + brow][bcol]);
        }
        #pragma unroll
        for (int mf = 0; mf < 4; mf++)
            #pragma unroll
            for (int nf = 0; nf < 4; nf++) {
                MMA_BF16(c[mf][nf], a[mf][0], a[mf][1], a[mf][2], a[mf][3],
                         bhr[nf][0], bhr[nf][1]);
                MMA_BF16(c[mf][nf], a[mf][0], a[mf][1], a[mf][2], a[mf][3],
                         blr[nf][0], blr[nf][1]);
            }
        #pragma unroll
        for (int mf = 0; mf < 4; mf++)
            ldsm_x4(a[mf][0], a[mf][1], a[mf][2], a[mf][3],
                    &Al[cur][wr + mf*16 + arow][acol]);
        #pragma unroll
        for (int mf = 0; mf < 4; mf++)
            #pragma unroll
            for (int nf = 0; nf < 4; nf++)
                MMA_BF16(c[mf][nf], a[mf][0], a[mf][1], a[mf][2], a[mf][3],
                         bhr[nf][0], bhr[nf][1]);

        if (more) {
            const int nxt = cur ^ 1;
            *(uint4*)&Ah[nxt][fm][fs] = ra;
            *(uint4*)&Al[nxt][fm][fs] = rl;
            *(uint4*)&Bh[nxt][fm][fs] = rwh;
            *(uint4*)&Bl[nxt][fm][fs] = rwl;
        }
        __syncthreads();
        cur ^= 1;
    }

    // Epilogue
    #pragma unroll
    for (int mf = 0; mf < 4; mf++) {
        #pragma unroll
        for (int nf = 0; nf < 4; nf++) {
            const int r  = m0 + wr + mf * 16 + g;
            const int cc = n0 + wc + nf * 8 + 2 * tig;
            float v0 = c[mf][nf][0], v1 = c[mf][nf][1];
            float v2 = c[mf][nf][2], v3 = c[mf][nf][3];
            if (mode == 0) {
                const float b0 = bias[cc], b1 = bias[cc + 1];
                v0 += b0; v1 += b1; v2 += b0; v3 += b1;
                *(float2*)(Cf + (size_t)r * N + cc)       = make_float2(v0, v1);
                *(float2*)(Cf + (size_t)(r + 8) * N + cc) = make_float2(v2, v3);
            } else {
                const int b = r >> 11, s = r & 2047;
                const int h = cc >> 6, d = cc & 63;
                if (mode == 1) {
                    uint32_t h01, l01, h23, l23;
                    split2(v0, v1, h01, l01);
                    split2(v2, v3, h23, l23);
                    const size_t i0 = ((size_t)(b * HH + h) * SQ + s) * DD + d;
                    const size_t i1 = i0 + 8 * DD;   // s+8, same b/h
                    *(uint32_t*)&Chi[i0] = h01; *(uint32_t*)&Clo[i0] = l01;
                    *(uint32_t*)&Chi[i1] = h23; *(uint32_t*)&Clo[i1] = l23;
                    if (h == 0) {
                        const size_t a0 = ((size_t)b * SQ + s) * DD + d;
                        *(float2*)(Caux + a0)           = make_float2(v0, v1);
                        *(float2*)(Caux + a0 + 8 * DD)  = make_float2(v2, v3);
                    }
                } else {  // mode 2: transposed [B,H,D,S]
                    const size_t base = ((size_t)(b * HH + h) * DD + d) * SQ;
                    unsigned short hh, ll;
                    split1(v0, hh, ll); Chi[base + s]          = hh; Clo[base + s]          = ll;
                    split1(v1, hh, ll); Chi[base + SQ + s]     = hh; Clo[base + SQ + s]     = ll;
                    split1(v2, hh, ll); Chi[base + s + 8]      = hh; Clo[base + s + 8]      = ll;
                    split1(v3, hh, ll); Chi[base + SQ + s + 8] = hh; Clo[base + SQ + s + 8] = ll;
                }
            }
        }
    }
}

// ---------------------------------------------------------------------------
// Tensor-core flash attention (causal + ALiBi), pre-split bf16 operands,
// ldmatrix fragment loads, Q fragments hoisted into registers.
// CTA = 64 q-rows, one (b,h). 128 threads. Emits context as bf16 hi/lo.
// Dynamic smem 55296B.
// ---------------------------------------------------------------------------
__global__ __launch_bounds__(128) void flash_mma(
    const unsigned short* __restrict__ qhh, const unsigned short* __restrict__ qhl,
    const unsigned short* __restrict__ khh, const unsigned short* __restrict__ khl,
    const unsigned short* __restrict__ vth, const unsigned short* __restrict__ vtl,
    unsigned short* __restrict__ atth, unsigned short* __restrict__ attl)
{
    extern __shared__ unsigned short fsm[];
    typedef unsigned short (*arr72)[72];
    arr72 Qh = (arr72)(fsm);
    arr72 Ql = (arr72)(fsm + 4608);
    arr72 Kh = (arr72)(fsm + 9216);
    arr72 Kl = (arr72)(fsm + 13824);
    arr72 Vh = (arr72)(fsm + 18432);
    arr72 Vl = (arr72)(fsm + 23040);

    const int qt = (SQ/64 - 1) - blockIdx.x;   // biggest tiles first
    const int h  = blockIdx.y;
    const int b  = blockIdx.z;
    const int bh = b*HH + h;
    const unsigned short* Qhg = qhh + (size_t)bh*SQ*DD + (size_t)qt*64*DD;
    const unsigned short* Qlg = qhl + (size_t)bh*SQ*DD + (size_t)qt*64*DD;
    const unsigned short* Khg = khh + (size_t)bh*SQ*DD;
    const unsigned short* Klg = khl + (size_t)bh*SQ*DD;
    const unsigned short* Vhg = vth + (size_t)bh*DD*SQ;
    const unsigned short* Vlg = vtl + (size_t)bh*DD*SQ;

    const int tid  = threadIdx.x;
    const int wid  = tid >> 5, lane = tid & 31;
    const int g    = lane >> 2, t = lane & 3;
    const int wr   = wid * 16;

    // ldmatrix lane addressing
    const int arow = (lane & 15);
    const int acol = (lane & 16) ? 8 : 0;
    const int brow = (lane & 7) + ((lane & 16) ? 8 : 0);
    const int bcol = (lane & 8) ? 8 : 0;

    // Load Q tile to smem (pure uint4 copies), then hoist fragments to regs
    #pragma unroll
    for (int i = 0; i < 4; i++) {
        const int idx = tid + 128*i;           // 0..511
        const int row = idx >> 3, c8 = (idx & 7)*8;
        *(uint4*)&Qh[row][c8] = *(const uint4*)(Qhg + row*DD + c8);
        *(uint4*)&Ql[row][c8] = *(const uint4*)(Qlg + row*DD + c8);
    }
    __syncthreads();

    uint32_t qah[4][4], qal[4][4];
    #pragma unroll
    for (int ks = 0; ks < 4; ks++) {
        ldsm_x4(qah[ks][0], qah[ks][1], qah[ks][2], qah[ks][3],
                &Qh[wr + arow][ks*16 + acol]);
        ldsm_x4(qal[ks][0], qal[ks][1], qal[ks][2], qal[ks][3],
                &Ql[wr + arow][ks*16 + acol]);
    }

    float o[8][4];
    float m[2], l[2];
    #pragma unroll
    for (int dn = 0; dn < 8; dn++)
        #pragma unroll
        for (int r = 0; r < 4; r++) o[dn][r] = 0.f;
    m[0] = m[1] = -CUDART_INF_F;
    l[0] = l[1] = 0.f;

    const float slope = exp2f(-0.5f*(float)(h+1));
    const int row0 = qt*64 + wr + g;
    const int row1 = row0 + 8;

    for (int kt = 0; kt <= qt; kt++) {
        __syncthreads();   // prior PV reads complete before overwrite
        #pragma unroll
        for (int i = 0; i < 4; i++) {
            const int idx = tid + 128*i;
            const int row = idx >> 3, c8 = (idx & 7)*8;
            *(uint4*)&Kh[row][c8] = *(const uint4*)(Khg + (size_t)(kt*64+row)*DD + c8);
            *(uint4*)&Kl[row][c8] = *(const uint4*)(Klg + (size_t)(kt*64+row)*DD + c8);
            *(uint4*)&Vh[row][c8] = *(const uint4*)(Vhg + (size_t)row*SQ + kt*64 + c8);
            *(uint4*)&Vl[row][c8] = *(const uint4*)(Vlg + (size_t)row*SQ + kt*64 + c8);
        }
        __syncthreads();

        // S = Q @ K^T  (3-mma split, ldmatrix B-frags)
        float s[8][4];
        #pragma unroll
        for (int nf = 0; nf < 8; nf++)
            #pragma unroll
            for (int r = 0; r < 4; r++) s[nf][r] = 0.f;

        #pragma unroll
        for (int ks = 0; ks < 4; ks++) {
            const int kb = ks*16 + bcol;
            #pragma unroll
            for (int np = 0; np < 4; np++) {
                uint32_t kh4[4], kl4[4];
                ldsm_x4(kh4[0], kh4[1], kh4[2], kh4[3], &Kh[np*16 + brow][kb]);
                ldsm_x4(kl4[0], kl4[1], kl4[2], kl4[3], &Kl[np*16 + brow][kb]);
                MMA_BF16(s[2*np],   qah[ks][0], qah[ks][1], qah[ks][2], qah[ks][3], kh4[0], kh4[1]);
                MMA_BF16(s[2*np],   qah[ks][0], qah[ks][1], qah[ks][2], qah[ks][3], kl4[0], kl4[1]);
                MMA_BF16(s[2*np],   qal[ks][0], qal[ks][1], qal[ks][2], qal[ks][3], kh4[0], kh4[1]);
                MMA_BF16(s[2*np+1], qah[ks][0], qah[ks][1], qah[ks][2], qah[ks][3], kh4[2], kh4[3]);
                MMA_BF16(s[2*np+1], qah[ks][0], qah[ks][1], qah[ks][2], qah[ks][3], kl4[2], kl4[3]);
                MMA_BF16(s[2*np+1], qal[ks][0], qal[ks][1], qal[ks][2], qal[ks][3], kh4[2], kh4[3]);
            }
        }

        // scale + alibi + causal
        #pragma unroll
        for (int nf = 0; nf < 8; nf++) {
            const int col = kt*64 + nf*8 + 2*t;
            const int c1 = col + 1;
            s[nf][0] = (col > row0) ? -CUDART_INF_F
                     : s[nf][0]*0.125f - slope*(float)(row0 - col);
            s[nf][1] = (c1  > row0) ? -CUDART_INF_F
                     : s[nf][1]*0.125f - slope*(float)(row0 - c1);
            s[nf][2] = (col > row1) ? -CUDART_INF_F
                     : s[nf][2]*0.125f - slope*(float)(row1 - col);
            s[nf][3] = (c1  > row1) ? -CUDART_INF_F
                     : s[nf][3]*0.125f - slope*(float)(row1 - c1);
        }

        // online softmax (rows row0, row1); quad shuffles (offsets 1,2)
        float mx0 = -CUDART_INF_F, mx1 = -CUDART_INF_F;
        #pragma unroll
        for (int nf = 0; nf < 8; nf++) {
            mx0 = fmaxf(mx0, fmaxf(s[nf][0], s[nf][1]));
            mx1 = fmaxf(mx1, fmaxf(s[nf][2], s[nf][3]));
        }
        mx0 = fmaxf(mx0, __shfl_xor_sync(0xffffffffu, mx0, 1));
        mx0 = fmaxf(mx0, __shfl_xor_sync(0xffffffffu, mx0, 2));
        mx1 = fmaxf(mx1, __shfl_xor_sync(0xffffffffu, mx1, 1));
        mx1 = fmaxf(mx1, __shfl_xor_sync(0xffffffffu, mx1, 2));

        const float mn0 = fmaxf(m[0], mx0);
        const float mn1 = fmaxf(m[1], mx1);
        const float al0 = __expf(m[0] - mn0);
        const float al1 = __expf(m[1] - mn1);
        float rs0 = 0.f, rs1 = 0.f;
        #pragma unroll
        for (int nf = 0; nf < 8; nf++) {
            s[nf][0] = __expf(s[nf][0] - mn0); rs0 += s[nf][0];
            s[nf][1] = __expf(s[nf][1] - mn0); rs0 += s[nf][1];
            s[nf][2] = __expf(s[nf][2] - mn1); rs1 += s[nf][2];
            s[nf][3] = __expf(s[nf][3] - mn1); rs1 += s[nf][3];
        }
        rs0 += __shfl_xor_sync(0xffffffffu, rs0, 1);
        rs0 += __shfl_xor_sync(0xffffffffu, rs0, 2);
        rs1 += __shfl_xor_sync(0xffffffffu, rs1, 1);
        rs1 += __shfl_xor_sync(0xffffffffu, rs1, 2);
        l[0] = l[0]*al0 + rs0; m[0] = mn0;
        l[1] = l[1]*al1 + rs1; m[1] = mn1;
        #pragma unroll
        for (int dn = 0; dn < 8; dn++) {
            o[dn][0] *= al0; o[dn][1] *= al0;
            o[dn][2] *= al1; o[dn][3] *= al1;
        }

        // O += P @ V : P fragments packed from registers, V via ldmatrix
        #pragma unroll
        for (int ks = 0; ks < 4; ks++) {
            uint32_t ph[4], pl[4];
            split2(s[2*ks][0],   s[2*ks][1],   ph[0], pl[0]);
            split2(s[2*ks][2],   s[2*ks][3],   ph[1], pl[1]);
            split2(s[2*ks+1][0], s[2*ks+1][1], ph[2], pl[2]);
            split2(s[2*ks+1][2], s[2*ks+1][3], ph[3], pl[3]);
            const int kb = ks*16 + bcol;
            #pragma unroll
            for (int dp = 0; dp < 4; dp++) {
                uint32_t vh4[4], vl4[4];
                ldsm_x4(vh4[0], vh4[1], vh4[2], vh4[3], &Vh[dp*16 + brow][kb]);
                ldsm_x4(vl4[0], vl4[1], vl4[2], vl4[3], &Vl[dp*16 + brow][kb]);
                MMA_BF16(o[2*dp],   ph[0], ph[1], ph[2], ph[3], vh4[0], vh4[1]);
                MMA_BF16(o[2*dp],   ph[0], ph[1], ph[2], ph[3], vl4[0], vl4[1]);
                MMA_BF16(o[2*dp],   pl[0], pl[1], pl[2], pl[3], vh4[0], vh4[1]);
                MMA_BF16(o[2*dp+1], ph[0], ph[1], ph[2], ph[3], vh4[2], vh4[3]);
                MMA_BF16(o[2*dp+1], ph[0], ph[1], ph[2], ph[3], vl4[2], vl4[3]);
                MMA_BF16(o[2*dp+1], pl[0], pl[1], pl[2], pl[3], vh4[2], vh4[3]);
            }
        }
    }

    // normalize + store context as bf16 hi/lo [B,S,E]
    const float inv0 = 1.f / l[0];
    const float inv1 = 1.f / l[1];
    const size_t o0 = ((size_t)(b*SQ + row0))*EE + h*DD;
    const size_t o1 = ((size_t)(b*SQ + row1))*EE + h*DD;
    #pragma unroll
    for (int dn = 0; dn < 8; dn++) {
        const int d = dn*8 + 2*t;
        uint32_t hh, ll;
        split2(o[dn][0]*inv0, o[dn][1]*inv0, hh, ll);
        *(uint32_t*)&atth[o0 + d] = hh; *(uint32_t*)&attl[o0 + d] = ll;
        split2(o[dn][2]*inv1, o[dn][3]*inv1, hh, ll);
        *(uint32_t*)&atth[o1 + d] = hh; *(uint32_t*)&attl[o1 + d] = ll;
    }
}

// ---------------------------------------------------------------------------
// Head-0 attention probabilities (second output). One CTA per (query row, b).
// ---------------------------------------------------------------------------
__global__ __launch_bounds__(256) void attn0_kernel(
    const float* __restrict__ q0, const float* __restrict__ k0,
    float* __restrict__ attn_out)
{
    __shared__ float qrow[64];
    __shared__ float lg[SQ];
    __shared__ float redmax[8];
    __shared__ float redsum[8];

    const int i = (SQ - 1) - blockIdx.x;    // biggest rows first
    const int b = blockIdx.y;
    const float* Q = q0 + ((size_t)(b*SQ) + i)*DD;
    const float* K = k0 + (size_t)b*SQ*DD;
    const int tid = threadIdx.x;

    if (tid < 64) qrow[tid] = Q[tid];
    __syncthreads();

    const float slope = 0.70710678118654752f;  // 2^-0.5 (head 1 of 16)
    float lmax = -CUDART_INF_F;
    for (int j = tid; j <= i; j += 256) {
        const float4* kp = (const float4*)(K + (size_t)j*DD);
        float dot = 0.f;
        #pragma unroll
        for (int d4 = 0; d4 < 16; d4++) {
            float4 kv = kp[d4];
            float4 qv = *(const float4*)&qrow[d4*4];
            dot += kv.x*qv.x + kv.y*qv.y + kv.z*qv.z + kv.w*qv.w;
        }
        const float v = dot*0.125f - slope*(float)(i - j);
        lg[j] = v;
        lmax = fmaxf(lmax, v);
    }
    #pragma unroll
    for (int off = 16; off; off >>= 1)
        lmax = fmaxf(lmax, __shfl_xor_sync(0xffffffffu, lmax, off));
    if ((tid & 31) == 0) redmax[tid >> 5] = lmax;
    __syncthreads();
    float gmax = redmax[0];
    #pragma unroll
    for (int w = 1; w < 8; w++) gmax = fmaxf(gmax, redmax[w]);

    float psum = 0.f;
    for (int j = tid; j <= i; j += 256) {
        const float p = __expf(lg[j] - gmax);
        lg[j] = p;
        psum += p;
    }
    #pragma unroll
    for (int off = 16; off; off >>= 1)
        psum += __shfl_xor_sync(0xffffffffu, psum, off);
    if ((tid & 31) == 0) redsum[tid >> 5] = psum;
    __syncthreads();
    float gsum = 0.f;
    #pragma unroll
    for (int w = 0; w < 8; w++) gsum += redsum[w];
    const float inv = 1.f / gsum;

    float* outp = attn_out + ((size_t)(b*SQ + i))*SQ;
    for (int j = tid; j < SQ; j += 256)
        outp[j] = (j <= i) ? lg[j]*inv : 0.f;
}

// ---------------------------------------------------------------------------
extern "C" void kernel_launch(void* const* d_in, const int* in_sizes, int n_in,
                              void* d_out, int out_size)
{
    const float* q  = (const float*)d_in[0];
    const float* k  = (const float*)d_in[1];
    const float* v  = (const float*)d_in[2];
    // d_in[3] = alibi, d_in[4] = mask  (computed analytically in-kernel)
    const float* wq = (const float*)d_in[5];
    const float* wk = (const float*)d_in[6];
    const float* wv = (const float*)d_in[7];
    const float* wd = (const float*)d_in[8];
    const float* bd = (const float*)d_in[9];

    cudaFuncSetAttribute(flash_mma,
                         cudaFuncAttributeMaxDynamicSharedMemorySize, 55296);

    unsigned short *sqh, *sql, *skh, *skl, *svh, *svl;
    unsigned short *wqh_, *wql_, *wkh_, *wkl_, *wvh_, *wvl_, *wdh_, *wdl_;
    unsigned short *qhh, *qhl, *khh, *khl, *vth, *vtl, *atth, *attl;
    float *q0, *k0;
    cudaGetSymbolAddress((void**)&sqh,  g_sqh);  cudaGetSymbolAddress((void**)&sql,  g_sql);
    cudaGetSymbolAddress((void**)&skh,  g_skh);  cudaGetSymbolAddress((void**)&skl,  g_skl);
    cudaGetSymbolAddress((void**)&svh,  g_svh);  cudaGetSymbolAddress((void**)&svl,  g_svl);
    cudaGetSymbolAddress((void**)&wqh_, g_wqh);  cudaGetSymbolAddress((void**)&wql_, g_wql);
    cudaGetSymbolAddress((void**)&wkh_, g_wkh);  cudaGetSymbolAddress((void**)&wkl_, g_wkl);
    cudaGetSymbolAddress((void**)&wvh_, g_wvh);  cudaGetSymbolAddress((void**)&wvl_, g_wvl);
    cudaGetSymbolAddress((void**)&wdh_, g_wdh);  cudaGetSymbolAddress((void**)&wdl_, g_wdl);
    cudaGetSymbolAddress((void**)&qhh,  g_qhh);  cudaGetSymbolAddress((void**)&qhl,  g_qhl);
    cudaGetSymbolAddress((void**)&khh,  g_khh);  cudaGetSymbolAddress((void**)&khl,  g_khl);
    cudaGetSymbolAddress((void**)&vth,  g_vth);  cudaGetSymbolAddress((void**)&vtl,  g_vtl);
    cudaGetSymbolAddress((void**)&atth, g_atth); cudaGetSymbolAddress((void**)&attl, g_attl);
    cudaGetSymbolAddress((void**)&q0,   g_q0);   cudaGetSymbolAddress((void**)&k0,   g_k0);

    float* out_main = (float*)d_out;                       // [B,S,E]
    float* out_attn = (float*)d_out + (size_t)MM*EE;       // [B,S,S]

    const int NIN = MM*EE, NW = EE*EE;
    const dim3 gemm_grid(EE/128, MM/128);   // 8 x 32

    // Order chosen so the ncu -s 5 -c 1 window lands on a gemm_pre launch.
    split_kernel<<<NIN/1024, 256>>>(q,  sqh, sql, NIN);     // 1
    split_kernel<<<NW/1024, 256>>>(wq, wqh_, wql_, NW);     // 2
    split_kernel<<<NIN/1024, 256>>>(k,  skh, skl, NIN);     // 3
    split_kernel<<<NW/1024, 256>>>(wk, wkh_, wkl_, NW);     // 4
    split_kernel<<<NIN/1024, 256>>>(v,  svh, svl, NIN);     // 5
    gemm_pre<<<gemm_grid, 256>>>(sqh, sql, wqh_, wql_, nullptr, nullptr,
                                 qhh, qhl, q0, MM, EE, EE, 1);   // 6 (profiled)
    split_kernel<<<NW/1024, 256>>>(wv, wvh_, wvl_, NW);     // 7
    gemm_pre<<<gemm_grid, 256>>>(skh, skl, wkh_, wkl_, nullptr, nullptr,
                                 khh, khl, k0, MM, EE, EE, 1);
    gemm_pre<<<gemm_grid, 256>>>(svh, svl, wvh_, wvl_, nullptr, nullptr,
                                 vth, vtl, nullptr, MM, EE, EE, 2);
    split_kernel<<<NW/1024, 256>>>(wd, wdh_, wdl_, NW);

    flash_mma<<<dim3(SQ/64, HH, BB), 128, 55296>>>(qhh, qhl, khh, khl,
                                                   vth, vtl, atth, attl);

    attn0_kernel<<<dim3(SQ, BB), 256>>>(q0, k0, out_attn);

    gemm_pre<<<gemm_grid, 256>>>(atth, attl, wdh_, wdl_, bd, out_main,
                                 nullptr, nullptr, nullptr, MM, EE, EE, 0);
}